// round 1
// baseline (speedup 1.0000x reference)
#include <cuda_runtime.h>

// ScaledDotProductAttention: B=8, S=2048, D=1024, fp32
// out[b,q,:] = softmax(q·K^T/32 + mask*NEG) @ V
//
// Round 0: fused per-q-tile kernel, fp32 FFMA path.
// 1 block = 16 queries; logits row block kept resident in SMEM (128 KB).

namespace {
constexpr int B_  = 8;
constexpr int S_  = 2048;
constexpr int D_  = 1024;
constexpr int MQ  = 16;     // queries per block
constexpr int NT  = 256;    // threads per block
constexpr int NB  = 128;    // phase-1 key tile
constexpr int DK  = 64;     // depth tile
constexpr int KPAD = 68;    // padded row (floats) for K/Q tiles
constexpr int DB  = 128;    // phase-3 output-column tile
constexpr int KT  = 64;     // phase-3 key tile
constexpr int VPAD = 132;   // padded row (floats) for V tile
constexpr float SCALE = 0.03125f;          // D^-0.5 = 1/32
constexpr float NEGV  = -1000000000.0f;

// shared memory layout (float offsets)
constexpr int OFF_LOGITS = 0;                    // MQ * S_
constexpr int OFF_MASK   = OFF_LOGITS + MQ * S_; // S_
constexpr int OFF_ROWINV = OFF_MASK + S_;        // MQ
constexpr int OFF_QS     = OFF_ROWINV + MQ;      // MQ * KPAD
constexpr int OFF_KV     = OFF_QS + MQ * KPAD;   // NB * KPAD (also V: KT*VPAD)
constexpr int SMEM_FLOATS = OFF_KV + NB * KPAD;
constexpr int SMEM_BYTES  = SMEM_FLOATS * (int)sizeof(float);
static_assert(NB * KPAD >= KT * VPAD, "shared K/V buffer too small");
static_assert(SMEM_BYTES <= 227 * 1024, "smem over budget");
}  // namespace

__device__ __forceinline__ float f4_get(const float4& v, int t) {
    switch (t) {
        case 0: return v.x;
        case 1: return v.y;
        case 2: return v.z;
        default: return v.w;
    }
}

__global__ void __launch_bounds__(NT, 1)
attn_kernel(const float* __restrict__ q, const float* __restrict__ k,
            const float* __restrict__ v, const float* __restrict__ mask,
            float* __restrict__ out) {
    extern __shared__ float sm[];

    const int tid = threadIdx.x;
    const int blk = blockIdx.x;
    const int b   = blk / (S_ / MQ);
    const int q0  = (blk % (S_ / MQ)) * MQ;

    const float* Qb = q + ((size_t)b * S_ + q0) * D_;
    const float* Kb = k + (size_t)b * S_ * D_;
    const float* Vb = v + (size_t)b * S_ * D_;
    const float* Mb = mask + (size_t)b * S_;

    // mask * NEG resident in smem
    for (int j = tid; j < S_; j += NT) sm[OFF_MASK + j] = Mb[j] * NEGV;

    const int tq = tid >> 6;   // 0..3  (covers 16 q rows, 4 per thread)
    const int tn = tid & 63;   // 0..63 (covers 128 cols, 2 per thread)

    // ===================== Phase 1: logits = Q @ K^T =====================
    for (int n0 = 0; n0 < S_; n0 += NB) {
        float acc0[4] = {0.f, 0.f, 0.f, 0.f};
        float acc1[4] = {0.f, 0.f, 0.f, 0.f};

        // register-staged double buffer for gmem loads
        float4 kreg[8];
        float4 qreg;
        {
            const int d0 = 0;
#pragma unroll
            for (int t = 0; t < 8; ++t) {
                int s = tid + t * NT;
                int j = s >> 4, c4 = s & 15;
                kreg[t] = *reinterpret_cast<const float4*>(
                    &Kb[(size_t)(n0 + j) * D_ + d0 + c4 * 4]);
            }
            qreg = *reinterpret_cast<const float4*>(
                &Qb[(size_t)(tid >> 4) * D_ + d0 + (tid & 15) * 4]);
        }

        for (int d0 = 0; d0 < D_; d0 += DK) {
            __syncthreads();  // prior compute done with smem tile
#pragma unroll
            for (int t = 0; t < 8; ++t) {
                int s = tid + t * NT;
                int j = s >> 4, c4 = s & 15;
                *reinterpret_cast<float4*>(&sm[OFF_KV + j * KPAD + c4 * 4]) = kreg[t];
            }
            *reinterpret_cast<float4*>(
                &sm[OFF_QS + (tid >> 4) * KPAD + (tid & 15) * 4]) = qreg;
            __syncthreads();

            if (d0 + DK < D_) {  // prefetch next depth tile (hidden under compute)
                const int dn = d0 + DK;
#pragma unroll
                for (int t = 0; t < 8; ++t) {
                    int s = tid + t * NT;
                    int j = s >> 4, c4 = s & 15;
                    kreg[t] = *reinterpret_cast<const float4*>(
                        &Kb[(size_t)(n0 + j) * D_ + dn + c4 * 4]);
                }
                qreg = *reinterpret_cast<const float4*>(
                    &Qb[(size_t)(tid >> 4) * D_ + dn + (tid & 15) * 4]);
            }

#pragma unroll
            for (int dd = 0; dd < DK; dd += 4) {
                float4 k0v = *reinterpret_cast<const float4*>(
                    &sm[OFF_KV + tn * KPAD + dd]);
                float4 k1v = *reinterpret_cast<const float4*>(
                    &sm[OFF_KV + (tn + 64) * KPAD + dd]);
#pragma unroll
                for (int i = 0; i < 4; ++i) {
                    float4 qv = *reinterpret_cast<const float4*>(
                        &sm[OFF_QS + (tq * 4 + i) * KPAD + dd]);
                    acc0[i] += qv.x * k0v.x + qv.y * k0v.y + qv.z * k0v.z + qv.w * k0v.w;
                    acc1[i] += qv.x * k1v.x + qv.y * k1v.y + qv.z * k1v.z + qv.w * k1v.w;
                }
            }
        }

#pragma unroll
        for (int i = 0; i < 4; ++i) {
            sm[OFF_LOGITS + (tq * 4 + i) * S_ + n0 + tn]      = acc0[i];
            sm[OFF_LOGITS + (tq * 4 + i) * S_ + n0 + tn + 64] = acc1[i];
        }
    }
    __syncthreads();

    // ===================== Phase 2: softmax (per-warp rows) =====================
    {
        const int warp = tid >> 5;
        const int lane = tid & 31;
#pragma unroll
        for (int rr = 0; rr < 2; ++rr) {
            const int r = warp * 2 + rr;
            float* row = &sm[OFF_LOGITS + r * S_];
            float m = -3.4e38f;
            for (int j = lane; j < S_; j += 32) {
                float val = row[j] * SCALE + sm[OFF_MASK + j];
                row[j] = val;
                m = fmaxf(m, val);
            }
#pragma unroll
            for (int off = 16; off > 0; off >>= 1)
                m = fmaxf(m, __shfl_xor_sync(0xFFFFFFFFu, m, off));
            float s = 0.f;
            for (int j = lane; j < S_; j += 32) {
                float e = __expf(row[j] - m);
                row[j] = e;
                s += e;
            }
#pragma unroll
            for (int off = 16; off > 0; off >>= 1)
                s += __shfl_xor_sync(0xFFFFFFFFu, s, off);
            if (lane == 0) sm[OFF_ROWINV + r] = 1.0f / s;
        }
    }
    __syncthreads();

    // ===================== Phase 3: out = P @ V =====================
    for (int dc0 = 0; dc0 < D_; dc0 += DB) {
        float acc0[4] = {0.f, 0.f, 0.f, 0.f};
        float acc1[4] = {0.f, 0.f, 0.f, 0.f};

        float4 vreg[8];
        {
            const int k0 = 0;
#pragma unroll
            for (int t = 0; t < 8; ++t) {
                int s = tid + t * NT;
                int kk = s >> 5, c4 = s & 31;
                vreg[t] = *reinterpret_cast<const float4*>(
                    &Vb[(size_t)(k0 + kk) * D_ + dc0 + c4 * 4]);
            }
        }

        for (int k0 = 0; k0 < S_; k0 += KT) {
            __syncthreads();
#pragma unroll
            for (int t = 0; t < 8; ++t) {
                int s = tid + t * NT;
                int kk = s >> 5, c4 = s & 31;
                *reinterpret_cast<float4*>(&sm[OFF_KV + kk * VPAD + c4 * 4]) = vreg[t];
            }
            __syncthreads();

            if (k0 + KT < S_) {
                const int kn = k0 + KT;
#pragma unroll
                for (int t = 0; t < 8; ++t) {
                    int s = tid + t * NT;
                    int kk = s >> 5, c4 = s & 31;
                    vreg[t] = *reinterpret_cast<const float4*>(
                        &Vb[(size_t)(kn + kk) * D_ + dc0 + c4 * 4]);
                }
            }

#pragma unroll
            for (int kk = 0; kk < KT; kk += 4) {
                float4 pv[4];
#pragma unroll
                for (int i = 0; i < 4; ++i)
                    pv[i] = *reinterpret_cast<const float4*>(
                        &sm[OFF_LOGITS + (tq * 4 + i) * S_ + k0 + kk]);
#pragma unroll
                for (int t = 0; t < 4; ++t) {
                    float v0 = sm[OFF_KV + (kk + t) * VPAD + tn];
                    float v1 = sm[OFF_KV + (kk + t) * VPAD + tn + 64];
#pragma unroll
                    for (int i = 0; i < 4; ++i) {
                        float p = f4_get(pv[i], t);
                        acc0[i] += p * v0;
                        acc1[i] += p * v1;
                    }
                }
            }
        }

#pragma unroll
        for (int i = 0; i < 4; ++i) {
            float inv = sm[OFF_ROWINV + tq * 4 + i];
            size_t rowbase = ((size_t)b * S_ + q0 + tq * 4 + i) * D_;
            out[rowbase + dc0 + tn]      = acc0[i] * inv;
            out[rowbase + dc0 + tn + 64] = acc1[i] * inv;
        }
    }
}

extern "C" void kernel_launch(void* const* d_in, const int* in_sizes, int n_in,
                              void* d_out, int out_size) {
    const float* q    = (const float*)d_in[0];
    const float* k    = (const float*)d_in[1];
    const float* v    = (const float*)d_in[2];
    const float* mask = (const float*)d_in[3];
    float* out = (float*)d_out;

    cudaFuncSetAttribute(attn_kernel,
                         cudaFuncAttributeMaxDynamicSharedMemorySize, SMEM_BYTES);

    dim3 grid(B_ * (S_ / MQ));  // 1024 blocks
    dim3 block(NT);
    attn_kernel<<<grid, block, SMEM_BYTES>>>(q, k, v, mask, out);
}

// round 3
// speedup vs baseline: 4.9527x; 4.9527x over previous
#include <cuda_runtime.h>
#include <cuda_bf16.h>
#include <cstdint>

// ScaledDotProductAttention B=8, S=2048, D=1024 fp32.
// Tensor-core path via baseline-PTX mma.sync bf16 (HMMA), hi/lo 3-pass split.

namespace {
constexpr int BN = 8, S_ = 2048, D_ = 1024;
constexpr float SCALE = 0.03125f;          // D^-0.5
constexpr float NEGV  = -1000000000.0f;

constexpr int TM = 128, TN = 128, TK = 64; // CTA tile
constexpr uint32_t BUF_B   = 16384;        // one 128x64 bf16 tile
constexpr uint32_t STAGE_B = 4 * BUF_B;    // Ah,Al,Bh,Bl
constexpr uint32_t SMEM_GEMM = 2 * STAGE_B + 1024;  // + mask row
}  // namespace

// ------------------------- scratch (device globals) -------------------------
__device__ __align__(128) __nv_bfloat16 g_qh[(size_t)BN * S_ * D_];
__device__ __align__(128) __nv_bfloat16 g_ql[(size_t)BN * S_ * D_];
__device__ __align__(128) __nv_bfloat16 g_kh[(size_t)BN * S_ * D_];
__device__ __align__(128) __nv_bfloat16 g_kl[(size_t)BN * S_ * D_];
__device__ __align__(128) __nv_bfloat16 g_vh[(size_t)BN * D_ * S_];  // V^T [b][d][s]
__device__ __align__(128) __nv_bfloat16 g_vl[(size_t)BN * D_ * S_];
__device__ __align__(128) __nv_bfloat16 g_ph[(size_t)BN * S_ * S_];
__device__ __align__(128) __nv_bfloat16 g_pl[(size_t)BN * S_ * S_];
__device__ __align__(128) float         g_s [(size_t)BN * S_ * S_]; // logits fp32

// ------------------------------- helpers ------------------------------------
__device__ __forceinline__ uint32_t smem_u32(const void* p) {
    uint32_t a;
    asm("{ .reg .u64 t; cvta.to.shared.u64 t, %1; cvt.u32.u64 %0, t; }"
        : "=r"(a) : "l"(p));
    return a;
}

#define LDSM4(r, addr) \
    asm volatile("ldmatrix.sync.aligned.m8n8.x4.shared.b16 {%0,%1,%2,%3}, [%4];" \
        : "=r"((r)[0]), "=r"((r)[1]), "=r"((r)[2]), "=r"((r)[3]) : "r"(addr))

#define MMA_BF16(d, a, b0, b1) \
    asm volatile("mma.sync.aligned.m16n8k16.row.col.f32.bf16.bf16.f32 " \
        "{%0,%1,%2,%3}, {%4,%5,%6,%7}, {%8,%9}, {%0,%1,%2,%3};" \
        : "+f"((d)[0]), "+f"((d)[1]), "+f"((d)[2]), "+f"((d)[3]) \
        : "r"((a)[0]), "r"((a)[1]), "r"((a)[2]), "r"((a)[3]), "r"(b0), "r"(b1))

__device__ __forceinline__ void split_bf16(float x, uint16_t& h, uint16_t& l) {
    __nv_bfloat16 hb = __float2bfloat16_rn(x);
    __nv_bfloat16 lb = __float2bfloat16_rn(x - __bfloat162float(hb));
    h = __bfloat16_as_ushort(hb);
    l = __bfloat16_as_ushort(lb);
}

__device__ __forceinline__ uint2 pack4h(const uint16_t* h) {
    return make_uint2((uint32_t)h[0] | ((uint32_t)h[1] << 16),
                      (uint32_t)h[2] | ((uint32_t)h[3] << 16));
}

// --------------------------- convert kernels --------------------------------
__global__ void __launch_bounds__(256) conv_qk_kernel(
    const float* __restrict__ src, __nv_bfloat16* __restrict__ dh,
    __nv_bfloat16* __restrict__ dl) {
    size_t e0 = ((size_t)blockIdx.x * 256 + threadIdx.x) * 4;
    float4 val = *reinterpret_cast<const float4*>(src + e0);
    uint16_t h[4], l[4];
    split_bf16(val.x, h[0], l[0]); split_bf16(val.y, h[1], l[1]);
    split_bf16(val.z, h[2], l[2]); split_bf16(val.w, h[3], l[3]);
    *reinterpret_cast<uint2*>(dh + e0) = pack4h(h);
    *reinterpret_cast<uint2*>(dl + e0) = pack4h(l);
}

// V[b][s][d] -> V^T[b][d][s] hi/lo
__global__ void __launch_bounds__(256) conv_v_kernel(const float* __restrict__ v) {
    __shared__ float tile[64][68];
    int b  = blockIdx.y;
    int st = blockIdx.x >> 4;   // s tile (0..31)
    int dt = blockIdx.x & 15;   // d tile (0..15)
    int tid = threadIdx.x;
    int i0 = tid >> 4, j4 = (tid & 15) * 4;
#pragma unroll
    for (int r = 0; r < 4; ++r) {
        int i = i0 + r * 16;
        float4 val = *reinterpret_cast<const float4*>(
            v + ((size_t)b * S_ + st * 64 + i) * D_ + dt * 64 + j4);
        tile[i][j4 + 0] = val.x; tile[i][j4 + 1] = val.y;
        tile[i][j4 + 2] = val.z; tile[i][j4 + 3] = val.w;
    }
    __syncthreads();
#pragma unroll
    for (int r = 0; r < 4; ++r) {
        int dl_ = i0 + r * 16;
        uint16_t h[4], l[4];
#pragma unroll
        for (int c = 0; c < 4; ++c) split_bf16(tile[j4 + c][dl_], h[c], l[c]);
        size_t off = ((size_t)b * D_ + dt * 64 + dl_) * S_ + st * 64 + j4;
        *reinterpret_cast<uint2*>(g_vh + off) = pack4h(h);
        *reinterpret_cast<uint2*>(g_vl + off) = pack4h(l);
    }
}

// ------------------------------ GEMM kernel ---------------------------------
// C[128x128] = Ah*Bh^T + Ah*Bl^T + Al*Bh^T  (A row-major [m][k], B rows [n][k])
// mode 0: epilogue C*SCALE + mask*NEG -> g_s ; mode 1: C -> out
__global__ void __launch_bounds__(256, 1)
gemm_kernel(const __nv_bfloat16* __restrict__ Ah, const __nv_bfloat16* __restrict__ Al,
            const __nv_bfloat16* __restrict__ Bh, const __nv_bfloat16* __restrict__ Bl,
            int lda, int ldb, size_t batchA, size_t batchB, int NC,
            int mode, const float* __restrict__ mask,
            float* __restrict__ Cp, int ldc) {
    extern __shared__ __align__(1024) char smg[];
    const uint32_t smb = smem_u32(smg);
    float* smmask = (float*)(smg + 2 * STAGE_B);

    const int tid = threadIdx.x;
    const int mt = blockIdx.x, nt = blockIdx.y, b = blockIdx.z;
    const int warp = tid >> 5, lane = tid & 31;
    const int wm = warp & 1, wn = warp >> 1;           // 2x4 warp grid
    const int lrow = lane & 15, lhalf = lane >> 4;

    const __nv_bfloat16* Ahp = Ah + (size_t)b * batchA + (size_t)(mt * TM) * lda;
    const __nv_bfloat16* Alp = Al + (size_t)b * batchA + (size_t)(mt * TM) * lda;
    const __nv_bfloat16* Bhp = Bh + (size_t)b * batchB + (size_t)(nt * TN) * ldb;
    const __nv_bfloat16* Blp = Bl + (size_t)b * batchB + (size_t)(nt * TN) * ldb;

    if (mode == 0) {
        if (tid < 128) smmask[tid] = mask[(size_t)b * S_ + nt * TN + tid] * NEGV;
    }

    auto load4 = [&](uint32_t dstbase, const __nv_bfloat16* src, int ld) {
#pragma unroll
        for (int i = 0; i < 4; ++i) {
            int id = tid + i * 256;
            int row = id >> 3, cc = id & 7;
            uint32_t dst = dstbase + row * 128 + ((cc ^ (row & 7)) << 4);
            const __nv_bfloat16* s = src + (size_t)row * ld + cc * 8;
            asm volatile("cp.async.cg.shared.global [%0], [%1], 16;"
                         :: "r"(dst), "l"(s));
        }
    };
    auto issue = [&](int c) {
        uint32_t sb = smb + (uint32_t)(c & 1) * STAGE_B;
        const int ko = c * TK;
        load4(sb,             Ahp + ko, lda);
        load4(sb + BUF_B,     Alp + ko, lda);
        load4(sb + 2 * BUF_B, Bhp + ko, ldb);
        load4(sb + 3 * BUF_B, Blp + ko, ldb);
        asm volatile("cp.async.commit_group;" ::: "memory");
    };

    float acc[4][4][4];
#pragma unroll
    for (int i = 0; i < 4; ++i)
#pragma unroll
        for (int n = 0; n < 4; ++n)
#pragma unroll
            for (int r = 0; r < 4; ++r) acc[i][n][r] = 0.f;

    issue(0);
    issue(1);

#pragma unroll 1
    for (int c = 0; c < NC; ++c) {
        if (c + 1 < NC) asm volatile("cp.async.wait_group 1;" ::: "memory");
        else            asm volatile("cp.async.wait_group 0;" ::: "memory");
        __syncthreads();

        const uint32_t sb = smb + (uint32_t)(c & 1) * STAGE_B;
#pragma unroll
        for (int ks = 0; ks < 4; ++ks) {
            uint32_t ah[4][4], al[4][4], bh[2][4], bl[2][4];
#pragma unroll
            for (int i = 0; i < 4; ++i) {
                int row = wm * 64 + i * 16 + lrow;
                uint32_t off = row * 128 + (((ks * 2 + lhalf) ^ (row & 7)) << 4);
                LDSM4(ah[i], sb + off);
                LDSM4(al[i], sb + BUF_B + off);
            }
#pragma unroll
            for (int j = 0; j < 2; ++j) {
                int row = wn * 32 + j * 16 + lrow;
                uint32_t off = row * 128 + (((ks * 2 + lhalf) ^ (row & 7)) << 4);
                LDSM4(bh[j], sb + 2 * BUF_B + off);
                LDSM4(bl[j], sb + 3 * BUF_B + off);
            }
#pragma unroll
            for (int i = 0; i < 4; ++i)
#pragma unroll
                for (int n = 0; n < 4; ++n) {
                    int j = n >> 1, s = n & 1;
                    MMA_BF16(acc[i][n], ah[i], bh[j][s], bh[j][s + 2]);
                    MMA_BF16(acc[i][n], ah[i], bl[j][s], bl[j][s + 2]);
                    MMA_BF16(acc[i][n], al[i], bh[j][s], bh[j][s + 2]);
                }
        }
        __syncthreads();
        if (c + 2 < NC) issue(c + 2);
    }

    // ------------------------------ epilogue --------------------------------
    const int r0 = mt * TM + wm * 64 + (lane >> 2);
    const int cl0 = wn * 32 + (lane & 3) * 2;          // local col in tile
#pragma unroll
    for (int i = 0; i < 4; ++i) {
#pragma unroll
        for (int n = 0; n < 4; ++n) {
            int cl = cl0 + n * 8;
            int col = nt * TN + cl;
            float v0 = acc[i][n][0], v1 = acc[i][n][1];
            float v2 = acc[i][n][2], v3 = acc[i][n][3];
            if (mode == 0) {
                float mk0 = smmask[cl], mk1 = smmask[cl + 1];
                v0 = v0 * SCALE + mk0; v1 = v1 * SCALE + mk1;
                v2 = v2 * SCALE + mk0; v3 = v3 * SCALE + mk1;
            }
            size_t rowa = (size_t)(b * S_ + r0 + i * 16) * ldc + col;
            size_t rowb = rowa + (size_t)8 * ldc;
            *reinterpret_cast<float2*>(Cp + rowa) = make_float2(v0, v1);
            *reinterpret_cast<float2*>(Cp + rowb) = make_float2(v2, v3);
        }
    }
}

// ------------------------------ softmax kernel ------------------------------
__global__ void __launch_bounds__(256) softmax_kernel() {
    __shared__ float red[8];
    const int r = blockIdx.x;                 // 0..16383 (b*2048+q)
    const int tid = threadIdx.x, lane = tid & 31, wid = tid >> 5;
    const float4* row4 = reinterpret_cast<const float4*>(g_s + (size_t)r * S_);
    float4 v0 = row4[tid], v1 = row4[tid + 256];

    float m = fmaxf(fmaxf(fmaxf(v0.x, v0.y), fmaxf(v0.z, v0.w)),
                    fmaxf(fmaxf(v1.x, v1.y), fmaxf(v1.z, v1.w)));
#pragma unroll
    for (int o = 16; o > 0; o >>= 1) m = fmaxf(m, __shfl_xor_sync(~0u, m, o));
    if (lane == 0) red[wid] = m;
    __syncthreads();
    m = red[0];
#pragma unroll
    for (int i = 1; i < 8; ++i) m = fmaxf(m, red[i]);
    __syncthreads();

    float e[8];
    e[0] = __expf(v0.x - m); e[1] = __expf(v0.y - m);
    e[2] = __expf(v0.z - m); e[3] = __expf(v0.w - m);
    e[4] = __expf(v1.x - m); e[5] = __expf(v1.y - m);
    e[6] = __expf(v1.z - m); e[7] = __expf(v1.w - m);
    float s = e[0] + e[1] + e[2] + e[3] + e[4] + e[5] + e[6] + e[7];
#pragma unroll
    for (int o = 16; o > 0; o >>= 1) s += __shfl_xor_sync(~0u, s, o);
    if (lane == 0) red[wid] = s;
    __syncthreads();
    s = red[0];
#pragma unroll
    for (int i = 1; i < 8; ++i) s += red[i];
    const float inv = 1.0f / s;

#pragma unroll
    for (int part = 0; part < 2; ++part) {
        size_t off = (size_t)r * S_ + (tid + part * 256) * 4;
        uint16_t h[4], l[4];
#pragma unroll
        for (int c = 0; c < 4; ++c) split_bf16(e[part * 4 + c] * inv, h[c], l[c]);
        *reinterpret_cast<uint2*>(g_ph + off) = pack4h(h);
        *reinterpret_cast<uint2*>(g_pl + off) = pack4h(l);
    }
}

// --------------------------------- launch -----------------------------------
extern "C" void kernel_launch(void* const* d_in, const int* in_sizes, int n_in,
                              void* d_out, int out_size) {
    const float* q    = (const float*)d_in[0];
    const float* k    = (const float*)d_in[1];
    const float* v    = (const float*)d_in[2];
    const float* mask = (const float*)d_in[3];
    float* out = (float*)d_out;

    cudaFuncSetAttribute(gemm_kernel,
                         cudaFuncAttributeMaxDynamicSharedMemorySize, SMEM_GEMM);

    __nv_bfloat16 *qh, *ql, *kh, *kl, *vh, *vl, *ph, *pl;
    float* sbuf;
    cudaGetSymbolAddress((void**)&qh, g_qh);
    cudaGetSymbolAddress((void**)&ql, g_ql);
    cudaGetSymbolAddress((void**)&kh, g_kh);
    cudaGetSymbolAddress((void**)&kl, g_kl);
    cudaGetSymbolAddress((void**)&vh, g_vh);
    cudaGetSymbolAddress((void**)&vl, g_vl);
    cudaGetSymbolAddress((void**)&ph, g_ph);
    cudaGetSymbolAddress((void**)&pl, g_pl);
    cudaGetSymbolAddress((void**)&sbuf, g_s);

    conv_qk_kernel<<<16384, 256>>>(q, qh, ql);
    conv_qk_kernel<<<16384, 256>>>(k, kh, kl);
    conv_v_kernel<<<dim3(512, 8), 256>>>(v);

    // GEMM1: logits[b,2048,2048] = Q @ K^T  (lda=ldb=1024, K=1024 -> NC=16)
    gemm_kernel<<<dim3(16, 16, 8), 256, SMEM_GEMM>>>(
        qh, ql, kh, kl, D_, D_, (size_t)S_ * D_, (size_t)S_ * D_, D_ / TK,
        0, mask, sbuf, S_);

    softmax_kernel<<<16384, 256>>>();

    // GEMM2: out[b,2048,1024] = P @ V  (A=P lda=2048, B=V^T ldb=2048, NC=32)
    gemm_kernel<<<dim3(16, 8, 8), 256, SMEM_GEMM>>>(
        ph, pl, vh, vl, S_, S_, (size_t)S_ * S_, (size_t)D_ * S_, S_ / TK,
        1, nullptr, out, D_);
}

// round 4
// speedup vs baseline: 7.0759x; 1.4287x over previous
#include <cuda_runtime.h>
#include <cuda_fp16.h>
#include <cstdint>

// ScaledDotProductAttention B=8, S=2048, D=1024 fp32.
// HMMA fp16 path: GEMM1 = hi/lo 3-pass (full precision), GEMM2 = single-pass fp16.

namespace {
constexpr int BN = 8, S_ = 2048, D_ = 1024;
constexpr float SCALE = 0.03125f;          // D^-0.5
constexpr float NEGV  = -1000000000.0f;

constexpr int TM = 128, TN = 128, TK = 64;
constexpr uint32_t BUF_B    = 16384;               // one 128x64 fp16 tile
constexpr uint32_t STAGE1_B = 4 * BUF_B;           // Ah,Al,Bh,Bl
constexpr uint32_t SMEM_G1  = 2 * STAGE1_B + 1024; // + mask row
constexpr uint32_t STAGE2_B = 2 * BUF_B;           // A,B
constexpr uint32_t SMEM_G2  = 2 * STAGE2_B;
}  // namespace

// ------------------------- scratch (device globals) -------------------------
__device__ __align__(128) __half g_qh[(size_t)BN * S_ * D_];
__device__ __align__(128) __half g_ql[(size_t)BN * S_ * D_];
__device__ __align__(128) __half g_kh[(size_t)BN * S_ * D_];
__device__ __align__(128) __half g_kl[(size_t)BN * S_ * D_];
__device__ __align__(128) __half g_vt[(size_t)BN * D_ * S_];  // V^T [b][d][s]
__device__ __align__(128) __half g_p [(size_t)BN * S_ * S_];  // softmaxed P
__device__ __align__(128) float  g_s [(size_t)BN * S_ * S_];  // logits fp32

// ------------------------------- helpers ------------------------------------
__device__ __forceinline__ uint32_t smem_u32(const void* p) {
    uint32_t a;
    asm("{ .reg .u64 t; cvta.to.shared.u64 t, %1; cvt.u32.u64 %0, t; }"
        : "=r"(a) : "l"(p));
    return a;
}

#define LDSM4(r, addr) \
    asm volatile("ldmatrix.sync.aligned.m8n8.x4.shared.b16 {%0,%1,%2,%3}, [%4];" \
        : "=r"((r)[0]), "=r"((r)[1]), "=r"((r)[2]), "=r"((r)[3]) : "r"(addr))

#define MMA_F16(d, a, b0, b1) \
    asm volatile("mma.sync.aligned.m16n8k16.row.col.f32.f16.f16.f32 " \
        "{%0,%1,%2,%3}, {%4,%5,%6,%7}, {%8,%9}, {%0,%1,%2,%3};" \
        : "+f"((d)[0]), "+f"((d)[1]), "+f"((d)[2]), "+f"((d)[3]) \
        : "r"((a)[0]), "r"((a)[1]), "r"((a)[2]), "r"((a)[3]), "r"(b0), "r"(b1))

__device__ __forceinline__ void split_f16(float x, uint16_t& h, uint16_t& l) {
    __half hb = __float2half_rn(x);
    __half lb = __float2half_rn(x - __half2float(hb));
    h = __half_as_ushort(hb);
    l = __half_as_ushort(lb);
}
__device__ __forceinline__ uint2 pack4(const uint16_t* h) {
    return make_uint2((uint32_t)h[0] | ((uint32_t)h[1] << 16),
                      (uint32_t)h[2] | ((uint32_t)h[3] << 16));
}

// --------------------------- convert kernels --------------------------------
__global__ void __launch_bounds__(256) conv_qk_kernel(
    const float* __restrict__ src, __half* __restrict__ dh,
    __half* __restrict__ dl) {
    size_t e0 = ((size_t)blockIdx.x * 256 + threadIdx.x) * 4;
    float4 val = *reinterpret_cast<const float4*>(src + e0);
    uint16_t h[4], l[4];
    split_f16(val.x, h[0], l[0]); split_f16(val.y, h[1], l[1]);
    split_f16(val.z, h[2], l[2]); split_f16(val.w, h[3], l[3]);
    *reinterpret_cast<uint2*>(dh + e0) = pack4(h);
    *reinterpret_cast<uint2*>(dl + e0) = pack4(l);
}

// V[b][s][d] -> V^T[b][d][s] fp16
__global__ void __launch_bounds__(256) conv_v_kernel(const float* __restrict__ v) {
    __shared__ float tile[64][68];
    int b  = blockIdx.y;
    int st = blockIdx.x >> 4;   // s tile (0..31)
    int dt = blockIdx.x & 15;   // d tile (0..15)
    int tid = threadIdx.x;
    int i0 = tid >> 4, j4 = (tid & 15) * 4;
#pragma unroll
    for (int r = 0; r < 4; ++r) {
        int i = i0 + r * 16;
        float4 val = *reinterpret_cast<const float4*>(
            v + ((size_t)b * S_ + st * 64 + i) * D_ + dt * 64 + j4);
        tile[i][j4 + 0] = val.x; tile[i][j4 + 1] = val.y;
        tile[i][j4 + 2] = val.z; tile[i][j4 + 3] = val.w;
    }
    __syncthreads();
#pragma unroll
    for (int r = 0; r < 4; ++r) {
        int dl_ = i0 + r * 16;
        uint16_t h[4];
#pragma unroll
        for (int c = 0; c < 4; ++c)
            h[c] = __half_as_ushort(__float2half_rn(tile[j4 + c][dl_]));
        size_t off = ((size_t)b * D_ + dt * 64 + dl_) * S_ + st * 64 + j4;
        *reinterpret_cast<uint2*>(g_vt + off) = pack4(h);
    }
}

// ---------------------- shared cp.async tile loader -------------------------
__device__ __forceinline__ void load_tile(uint32_t dstbase, const __half* src,
                                          int ld, int tid) {
#pragma unroll
    for (int i = 0; i < 4; ++i) {
        int id = tid + i * 256;
        int row = id >> 3, cc = id & 7;
        uint32_t dst = dstbase + row * 128 + ((cc ^ (row & 7)) << 4);
        const __half* s = src + (size_t)row * ld + cc * 8;
        asm volatile("cp.async.cg.shared.global [%0], [%1], 16;"
                     :: "r"(dst), "l"(s));
    }
}

// -------------------------- GEMM1: logits (3-pass) --------------------------
__global__ void __launch_bounds__(256, 1)
gemm1_kernel(const __half* __restrict__ Ah, const __half* __restrict__ Al,
             const __half* __restrict__ Bh, const __half* __restrict__ Bl,
             const float* __restrict__ mask, float* __restrict__ Cp) {
    extern __shared__ __align__(1024) char smg[];
    const uint32_t smb = smem_u32(smg);
    float* smmask = (float*)(smg + 2 * STAGE1_B);

    const int tid = threadIdx.x;
    const int mt = blockIdx.x, nt = blockIdx.y, b = blockIdx.z;
    const int warp = tid >> 5, lane = tid & 31;
    const int wm = warp & 1, wn = warp >> 1;
    const int lrow = lane & 15, lhalf = lane >> 4;
    constexpr int NC = D_ / TK;  // 16

    const __half* Ahp = Ah + ((size_t)b * S_ + mt * TM) * D_;
    const __half* Alp = Al + ((size_t)b * S_ + mt * TM) * D_;
    const __half* Bhp = Bh + ((size_t)b * S_ + nt * TN) * D_;
    const __half* Blp = Bl + ((size_t)b * S_ + nt * TN) * D_;

    if (tid < 128) smmask[tid] = mask[(size_t)b * S_ + nt * TN + tid] * NEGV;

    auto issue = [&](int c) {
        uint32_t sb = smb + (uint32_t)(c & 1) * STAGE1_B;
        const int ko = c * TK;
        load_tile(sb,             Ahp + ko, D_, tid);
        load_tile(sb + BUF_B,     Alp + ko, D_, tid);
        load_tile(sb + 2 * BUF_B, Bhp + ko, D_, tid);
        load_tile(sb + 3 * BUF_B, Blp + ko, D_, tid);
        asm volatile("cp.async.commit_group;" ::: "memory");
    };

    float acc[4][4][4];
#pragma unroll
    for (int i = 0; i < 4; ++i)
#pragma unroll
        for (int n = 0; n < 4; ++n)
#pragma unroll
            for (int r = 0; r < 4; ++r) acc[i][n][r] = 0.f;

    issue(0);
    issue(1);

#pragma unroll 1
    for (int c = 0; c < NC; ++c) {
        if (c + 1 < NC) asm volatile("cp.async.wait_group 1;" ::: "memory");
        else            asm volatile("cp.async.wait_group 0;" ::: "memory");
        __syncthreads();

        const uint32_t sb = smb + (uint32_t)(c & 1) * STAGE1_B;
#pragma unroll
        for (int ks = 0; ks < 4; ++ks) {
            uint32_t ah[4][4], al[4][4], bh[2][4], bl[2][4];
#pragma unroll
            for (int i = 0; i < 4; ++i) {
                int row = wm * 64 + i * 16 + lrow;
                uint32_t off = row * 128 + (((ks * 2 + lhalf) ^ (row & 7)) << 4);
                LDSM4(ah[i], sb + off);
                LDSM4(al[i], sb + BUF_B + off);
            }
#pragma unroll
            for (int j = 0; j < 2; ++j) {
                int row = wn * 32 + j * 16 + lrow;
                uint32_t off = row * 128 + (((ks * 2 + lhalf) ^ (row & 7)) << 4);
                LDSM4(bh[j], sb + 2 * BUF_B + off);
                LDSM4(bl[j], sb + 3 * BUF_B + off);
            }
            // pass-major: 16 independent accumulator chains per pass
#pragma unroll
            for (int i = 0; i < 4; ++i)
#pragma unroll
                for (int n = 0; n < 4; ++n) {
                    int j = n >> 1, s = n & 1;
                    MMA_F16(acc[i][n], ah[i], bh[j][s], bh[j][s + 2]);
                }
#pragma unroll
            for (int i = 0; i < 4; ++i)
#pragma unroll
                for (int n = 0; n < 4; ++n) {
                    int j = n >> 1, s = n & 1;
                    MMA_F16(acc[i][n], ah[i], bl[j][s], bl[j][s + 2]);
                }
#pragma unroll
            for (int i = 0; i < 4; ++i)
#pragma unroll
                for (int n = 0; n < 4; ++n) {
                    int j = n >> 1, s = n & 1;
                    MMA_F16(acc[i][n], al[i], bh[j][s], bh[j][s + 2]);
                }
        }
        __syncthreads();
        if (c + 2 < NC) issue(c + 2);
    }

    const int r0 = mt * TM + wm * 64 + (lane >> 2);
    const int cl0 = wn * 32 + (lane & 3) * 2;
#pragma unroll
    for (int i = 0; i < 4; ++i) {
#pragma unroll
        for (int n = 0; n < 4; ++n) {
            int cl = cl0 + n * 8;
            float mk0 = smmask[cl], mk1 = smmask[cl + 1];
            float v0 = acc[i][n][0] * SCALE + mk0;
            float v1 = acc[i][n][1] * SCALE + mk1;
            float v2 = acc[i][n][2] * SCALE + mk0;
            float v3 = acc[i][n][3] * SCALE + mk1;
            size_t rowa = (size_t)(b * S_ + r0 + i * 16) * S_ + nt * TN + cl;
            size_t rowb = rowa + (size_t)8 * S_;
            *reinterpret_cast<float2*>(Cp + rowa) = make_float2(v0, v1);
            *reinterpret_cast<float2*>(Cp + rowb) = make_float2(v2, v3);
        }
    }
}

// -------------------------- GEMM2: out = P @ V (1-pass) ---------------------
__global__ void __launch_bounds__(256, 2)
gemm2_kernel(const __half* __restrict__ A, const __half* __restrict__ Bt,
             float* __restrict__ Cp) {
    extern __shared__ __align__(1024) char smg[];
    const uint32_t smb = smem_u32(smg);

    const int tid = threadIdx.x;
    const int mt = blockIdx.x, nt = blockIdx.y, b = blockIdx.z;
    const int warp = tid >> 5, lane = tid & 31;
    const int wm = warp & 1, wn = warp >> 1;
    const int lrow = lane & 15, lhalf = lane >> 4;
    constexpr int NC = S_ / TK;  // 32

    const __half* Ap = A  + ((size_t)b * S_ + mt * TM) * S_;
    const __half* Bp = Bt + ((size_t)b * D_ + nt * TN) * S_;

    auto issue = [&](int c) {
        uint32_t sb = smb + (uint32_t)(c & 1) * STAGE2_B;
        const int ko = c * TK;
        load_tile(sb,         Ap + ko, S_, tid);
        load_tile(sb + BUF_B, Bp + ko, S_, tid);
        asm volatile("cp.async.commit_group;" ::: "memory");
    };

    float acc[4][4][4];
#pragma unroll
    for (int i = 0; i < 4; ++i)
#pragma unroll
        for (int n = 0; n < 4; ++n)
#pragma unroll
            for (int r = 0; r < 4; ++r) acc[i][n][r] = 0.f;

    issue(0);
    issue(1);

#pragma unroll 1
    for (int c = 0; c < NC; ++c) {
        if (c + 1 < NC) asm volatile("cp.async.wait_group 1;" ::: "memory");
        else            asm volatile("cp.async.wait_group 0;" ::: "memory");
        __syncthreads();

        const uint32_t sb = smb + (uint32_t)(c & 1) * STAGE2_B;
#pragma unroll
        for (int ks = 0; ks < 4; ++ks) {
            uint32_t ah[4][4], bh[2][4];
#pragma unroll
            for (int i = 0; i < 4; ++i) {
                int row = wm * 64 + i * 16 + lrow;
                uint32_t off = row * 128 + (((ks * 2 + lhalf) ^ (row & 7)) << 4);
                LDSM4(ah[i], sb + off);
            }
#pragma unroll
            for (int j = 0; j < 2; ++j) {
                int row = wn * 32 + j * 16 + lrow;
                uint32_t off = row * 128 + (((ks * 2 + lhalf) ^ (row & 7)) << 4);
                LDSM4(bh[j], sb + BUF_B + off);
            }
#pragma unroll
            for (int i = 0; i < 4; ++i)
#pragma unroll
                for (int n = 0; n < 4; ++n) {
                    int j = n >> 1, s = n & 1;
                    MMA_F16(acc[i][n], ah[i], bh[j][s], bh[j][s + 2]);
                }
        }
        __syncthreads();
        if (c + 2 < NC) issue(c + 2);
    }

    const int r0 = mt * TM + wm * 64 + (lane >> 2);
    const int cl0 = wn * 32 + (lane & 3) * 2;
#pragma unroll
    for (int i = 0; i < 4; ++i) {
#pragma unroll
        for (int n = 0; n < 4; ++n) {
            int col = nt * TN + cl0 + n * 8;
            size_t rowa = (size_t)(b * S_ + r0 + i * 16) * D_ + col;
            size_t rowb = rowa + (size_t)8 * D_;
            *reinterpret_cast<float2*>(Cp + rowa) =
                make_float2(acc[i][n][0], acc[i][n][1]);
            *reinterpret_cast<float2*>(Cp + rowb) =
                make_float2(acc[i][n][2], acc[i][n][3]);
        }
    }
}

// ------------------------------ softmax kernel ------------------------------
__global__ void __launch_bounds__(256) softmax_kernel() {
    __shared__ float red[8];
    const int r = blockIdx.x;                 // b*2048+q
    const int tid = threadIdx.x, lane = tid & 31, wid = tid >> 5;
    const float4* row4 = reinterpret_cast<const float4*>(g_s + (size_t)r * S_);
    float4 v0 = row4[tid], v1 = row4[tid + 256];

    float m = fmaxf(fmaxf(fmaxf(v0.x, v0.y), fmaxf(v0.z, v0.w)),
                    fmaxf(fmaxf(v1.x, v1.y), fmaxf(v1.z, v1.w)));
#pragma unroll
    for (int o = 16; o > 0; o >>= 1) m = fmaxf(m, __shfl_xor_sync(~0u, m, o));
    if (lane == 0) red[wid] = m;
    __syncthreads();
    m = red[0];
#pragma unroll
    for (int i = 1; i < 8; ++i) m = fmaxf(m, red[i]);
    __syncthreads();

    float e[8];
    e[0] = __expf(v0.x - m); e[1] = __expf(v0.y - m);
    e[2] = __expf(v0.z - m); e[3] = __expf(v0.w - m);
    e[4] = __expf(v1.x - m); e[5] = __expf(v1.y - m);
    e[6] = __expf(v1.z - m); e[7] = __expf(v1.w - m);
    float s = e[0] + e[1] + e[2] + e[3] + e[4] + e[5] + e[6] + e[7];
#pragma unroll
    for (int o = 16; o > 0; o >>= 1) s += __shfl_xor_sync(~0u, s, o);
    if (lane == 0) red[wid] = s;
    __syncthreads();
    s = red[0];
#pragma unroll
    for (int i = 1; i < 8; ++i) s += red[i];
    const float inv = 1.0f / s;

#pragma unroll
    for (int part = 0; part < 2; ++part) {
        size_t off = (size_t)r * S_ + (tid + part * 256) * 4;
        uint16_t h[4];
#pragma unroll
        for (int c = 0; c < 4; ++c)
            h[c] = __half_as_ushort(__float2half_rn(e[part * 4 + c] * inv));
        *reinterpret_cast<uint2*>(g_p + off) = pack4(h);
    }
}

// --------------------------------- launch -----------------------------------
extern "C" void kernel_launch(void* const* d_in, const int* in_sizes, int n_in,
                              void* d_out, int out_size) {
    const float* q    = (const float*)d_in[0];
    const float* k    = (const float*)d_in[1];
    const float* v    = (const float*)d_in[2];
    const float* mask = (const float*)d_in[3];
    float* out = (float*)d_out;

    cudaFuncSetAttribute(gemm1_kernel,
                         cudaFuncAttributeMaxDynamicSharedMemorySize, SMEM_G1);
    cudaFuncSetAttribute(gemm2_kernel,
                         cudaFuncAttributeMaxDynamicSharedMemorySize, SMEM_G2);

    __half *qh, *ql, *kh, *kl, *vt, *p;
    float* sbuf;
    cudaGetSymbolAddress((void**)&qh, g_qh);
    cudaGetSymbolAddress((void**)&ql, g_ql);
    cudaGetSymbolAddress((void**)&kh, g_kh);
    cudaGetSymbolAddress((void**)&kl, g_kl);
    cudaGetSymbolAddress((void**)&vt, g_vt);
    cudaGetSymbolAddress((void**)&p,  g_p);
    cudaGetSymbolAddress((void**)&sbuf, g_s);

    conv_qk_kernel<<<16384, 256>>>(q, qh, ql);
    conv_qk_kernel<<<16384, 256>>>(k, kh, kl);
    conv_v_kernel<<<dim3(512, 8), 256>>>(v);

    gemm1_kernel<<<dim3(16, 16, 8), 256, SMEM_G1>>>(qh, ql, kh, kl, mask, sbuf);
    softmax_kernel<<<16384, 256>>>();
    gemm2_kernel<<<dim3(16, 8, 8), 256, SMEM_G2>>>(p, vt, out);
}

// round 5
// speedup vs baseline: 9.8054x; 1.3857x over previous
#include <cuda_runtime.h>
#include <cuda_fp16.h>
#include <cstdint>

// ScaledDotProductAttention B=8, S=2048, D=1024 fp32.
// HMMA fp16: GEMM1 = 2-pass Qh*(Kh+Kl) @ occ2, GEMM2 = single-pass fp16.

namespace {
constexpr int BN = 8, S_ = 2048, D_ = 1024;
constexpr float SCALE = 0.03125f;          // D^-0.5
constexpr float NEGV  = -1000000000.0f;

constexpr int TM = 128, TN = 128, TK = 64;
constexpr uint32_t BUF_B    = 16384;               // one 128x64 fp16 tile
constexpr uint32_t STAGE1_B = 3 * BUF_B;           // Ah,Bh,Bl
constexpr uint32_t SMEM_G1  = 2 * STAGE1_B + 1024; // + mask row  (~97KB)
constexpr uint32_t STAGE2_B = 2 * BUF_B;           // A,B
constexpr uint32_t SMEM_G2  = 2 * STAGE2_B;        // 64KB
}  // namespace

// ------------------------- scratch (device globals) -------------------------
__device__ __align__(128) __half g_qh[(size_t)BN * S_ * D_];
__device__ __align__(128) __half g_kh[(size_t)BN * S_ * D_];
__device__ __align__(128) __half g_kl[(size_t)BN * S_ * D_];
__device__ __align__(128) __half g_vt[(size_t)BN * D_ * S_];  // V^T [b][d][s]
__device__ __align__(128) __half g_p [(size_t)BN * S_ * S_];  // softmaxed P
__device__ __align__(128) float  g_s [(size_t)BN * S_ * S_];  // logits fp32

// ------------------------------- helpers ------------------------------------
__device__ __forceinline__ uint32_t smem_u32(const void* p) {
    uint32_t a;
    asm("{ .reg .u64 t; cvta.to.shared.u64 t, %1; cvt.u32.u64 %0, t; }"
        : "=r"(a) : "l"(p));
    return a;
}

#define LDSM4(r, addr) \
    asm volatile("ldmatrix.sync.aligned.m8n8.x4.shared.b16 {%0,%1,%2,%3}, [%4];" \
        : "=r"((r)[0]), "=r"((r)[1]), "=r"((r)[2]), "=r"((r)[3]) : "r"(addr))

#define MMA_F16(d, a, b0, b1) \
    asm volatile("mma.sync.aligned.m16n8k16.row.col.f32.f16.f16.f32 " \
        "{%0,%1,%2,%3}, {%4,%5,%6,%7}, {%8,%9}, {%0,%1,%2,%3};" \
        : "+f"((d)[0]), "+f"((d)[1]), "+f"((d)[2]), "+f"((d)[3]) \
        : "r"((a)[0]), "r"((a)[1]), "r"((a)[2]), "r"((a)[3]), "r"(b0), "r"(b1))

__device__ __forceinline__ void split_f16(float x, uint16_t& h, uint16_t& l) {
    __half hb = __float2half_rn(x);
    __half lb = __float2half_rn(x - __half2float(hb));
    h = __half_as_ushort(hb);
    l = __half_as_ushort(lb);
}
__device__ __forceinline__ uint2 pack4(const uint16_t* h) {
    return make_uint2((uint32_t)h[0] | ((uint32_t)h[1] << 16),
                      (uint32_t)h[2] | ((uint32_t)h[3] << 16));
}

// --------------------------- convert kernels --------------------------------
// Q: hi only
__global__ void __launch_bounds__(256) conv_q_kernel(const float* __restrict__ src) {
    size_t e0 = ((size_t)blockIdx.x * 256 + threadIdx.x) * 4;
    float4 val = *reinterpret_cast<const float4*>(src + e0);
    uint16_t h[4];
    h[0] = __half_as_ushort(__float2half_rn(val.x));
    h[1] = __half_as_ushort(__float2half_rn(val.y));
    h[2] = __half_as_ushort(__float2half_rn(val.z));
    h[3] = __half_as_ushort(__float2half_rn(val.w));
    *reinterpret_cast<uint2*>(g_qh + e0) = pack4(h);
}

// K: hi + lo
__global__ void __launch_bounds__(256) conv_k_kernel(const float* __restrict__ src) {
    size_t e0 = ((size_t)blockIdx.x * 256 + threadIdx.x) * 4;
    float4 val = *reinterpret_cast<const float4*>(src + e0);
    uint16_t h[4], l[4];
    split_f16(val.x, h[0], l[0]); split_f16(val.y, h[1], l[1]);
    split_f16(val.z, h[2], l[2]); split_f16(val.w, h[3], l[3]);
    *reinterpret_cast<uint2*>(g_kh + e0) = pack4(h);
    *reinterpret_cast<uint2*>(g_kl + e0) = pack4(l);
}

// V[b][s][d] -> V^T[b][d][s] fp16
__global__ void __launch_bounds__(256) conv_v_kernel(const float* __restrict__ v) {
    __shared__ float tile[64][68];
    int b  = blockIdx.y;
    int st = blockIdx.x >> 4;   // s tile (0..31)
    int dt = blockIdx.x & 15;   // d tile (0..15)
    int tid = threadIdx.x;
    int i0 = tid >> 4, j4 = (tid & 15) * 4;
#pragma unroll
    for (int r = 0; r < 4; ++r) {
        int i = i0 + r * 16;
        float4 val = *reinterpret_cast<const float4*>(
            v + ((size_t)b * S_ + st * 64 + i) * D_ + dt * 64 + j4);
        tile[i][j4 + 0] = val.x; tile[i][j4 + 1] = val.y;
        tile[i][j4 + 2] = val.z; tile[i][j4 + 3] = val.w;
    }
    __syncthreads();
#pragma unroll
    for (int r = 0; r < 4; ++r) {
        int dl_ = i0 + r * 16;
        uint16_t h[4];
#pragma unroll
        for (int c = 0; c < 4; ++c)
            h[c] = __half_as_ushort(__float2half_rn(tile[j4 + c][dl_]));
        size_t off = ((size_t)b * D_ + dt * 64 + dl_) * S_ + st * 64 + j4;
        *reinterpret_cast<uint2*>(g_vt + off) = pack4(h);
    }
}

// ---------------------- shared cp.async tile loader -------------------------
__device__ __forceinline__ void load_tile(uint32_t dstbase, const __half* src,
                                          int ld, int tid) {
#pragma unroll
    for (int i = 0; i < 4; ++i) {
        int id = tid + i * 256;
        int row = id >> 3, cc = id & 7;
        uint32_t dst = dstbase + row * 128 + ((cc ^ (row & 7)) << 4);
        const __half* s = src + (size_t)row * ld + cc * 8;
        asm volatile("cp.async.cg.shared.global [%0], [%1], 16;"
                     :: "r"(dst), "l"(s));
    }
}

// -------------------------- GEMM1: logits (2-pass) --------------------------
__global__ void __launch_bounds__(256, 2)
gemm1_kernel(const __half* __restrict__ Ah, const __half* __restrict__ Bh,
             const __half* __restrict__ Bl, const float* __restrict__ mask,
             float* __restrict__ Cp) {
    extern __shared__ __align__(1024) char smg[];
    const uint32_t smb = smem_u32(smg);
    float* smmask = (float*)(smg + 2 * STAGE1_B);

    const int tid = threadIdx.x;
    const int mt = blockIdx.x, nt = blockIdx.y, b = blockIdx.z;
    const int warp = tid >> 5, lane = tid & 31;
    const int wm = warp & 1, wn = warp >> 1;
    const int lrow = lane & 15, lhalf = lane >> 4;
    constexpr int NC = D_ / TK;  // 16

    const __half* Ahp = Ah + ((size_t)b * S_ + mt * TM) * D_;
    const __half* Bhp = Bh + ((size_t)b * S_ + nt * TN) * D_;
    const __half* Blp = Bl + ((size_t)b * S_ + nt * TN) * D_;

    if (tid < 128) smmask[tid] = mask[(size_t)b * S_ + nt * TN + tid] * NEGV;

    auto issue = [&](int c) {
        uint32_t sb = smb + (uint32_t)(c & 1) * STAGE1_B;
        const int ko = c * TK;
        load_tile(sb,             Ahp + ko, D_, tid);
        load_tile(sb + BUF_B,     Bhp + ko, D_, tid);
        load_tile(sb + 2 * BUF_B, Blp + ko, D_, tid);
        asm volatile("cp.async.commit_group;" ::: "memory");
    };

    float acc[4][4][4];
#pragma unroll
    for (int i = 0; i < 4; ++i)
#pragma unroll
        for (int n = 0; n < 4; ++n)
#pragma unroll
            for (int r = 0; r < 4; ++r) acc[i][n][r] = 0.f;

    issue(0);
    issue(1);

#pragma unroll 1
    for (int c = 0; c < NC; ++c) {
        if (c + 1 < NC) asm volatile("cp.async.wait_group 1;" ::: "memory");
        else            asm volatile("cp.async.wait_group 0;" ::: "memory");
        __syncthreads();

        const uint32_t sb = smb + (uint32_t)(c & 1) * STAGE1_B;
#pragma unroll
        for (int ks = 0; ks < 4; ++ks) {
            uint32_t ah[4][4], bh[2][4], bl[2][4];
#pragma unroll
            for (int i = 0; i < 4; ++i) {
                int row = wm * 64 + i * 16 + lrow;
                uint32_t off = row * 128 + (((ks * 2 + lhalf) ^ (row & 7)) << 4);
                LDSM4(ah[i], sb + off);
            }
#pragma unroll
            for (int j = 0; j < 2; ++j) {
                int row = wn * 32 + j * 16 + lrow;
                uint32_t off = row * 128 + (((ks * 2 + lhalf) ^ (row & 7)) << 4);
                LDSM4(bh[j], sb + BUF_B + off);
                LDSM4(bl[j], sb + 2 * BUF_B + off);
            }
#pragma unroll
            for (int i = 0; i < 4; ++i)
#pragma unroll
                for (int n = 0; n < 4; ++n) {
                    int j = n >> 1, s = n & 1;
                    MMA_F16(acc[i][n], ah[i], bh[j][s], bh[j][s + 2]);
                }
#pragma unroll
            for (int i = 0; i < 4; ++i)
#pragma unroll
                for (int n = 0; n < 4; ++n) {
                    int j = n >> 1, s = n & 1;
                    MMA_F16(acc[i][n], ah[i], bl[j][s], bl[j][s + 2]);
                }
        }
        __syncthreads();
        if (c + 2 < NC) issue(c + 2);
    }

    const int r0 = mt * TM + wm * 64 + (lane >> 2);
    const int cl0 = wn * 32 + (lane & 3) * 2;
#pragma unroll
    for (int i = 0; i < 4; ++i) {
#pragma unroll
        for (int n = 0; n < 4; ++n) {
            int cl = cl0 + n * 8;
            float mk0 = smmask[cl], mk1 = smmask[cl + 1];
            float v0 = acc[i][n][0] * SCALE + mk0;
            float v1 = acc[i][n][1] * SCALE + mk1;
            float v2 = acc[i][n][2] * SCALE + mk0;
            float v3 = acc[i][n][3] * SCALE + mk1;
            size_t rowa = (size_t)(b * S_ + r0 + i * 16) * S_ + nt * TN + cl;
            size_t rowb = rowa + (size_t)8 * S_;
            *reinterpret_cast<float2*>(Cp + rowa) = make_float2(v0, v1);
            *reinterpret_cast<float2*>(Cp + rowb) = make_float2(v2, v3);
        }
    }
}

// -------------------------- GEMM2: out = P @ V (1-pass) ---------------------
__global__ void __launch_bounds__(256, 2)
gemm2_kernel(const __half* __restrict__ A, const __half* __restrict__ Bt,
             float* __restrict__ Cp) {
    extern __shared__ __align__(1024) char smg[];
    const uint32_t smb = smem_u32(smg);

    const int tid = threadIdx.x;
    const int mt = blockIdx.x, nt = blockIdx.y, b = blockIdx.z;
    const int warp = tid >> 5, lane = tid & 31;
    const int wm = warp & 1, wn = warp >> 1;
    const int lrow = lane & 15, lhalf = lane >> 4;
    constexpr int NC = S_ / TK;  // 32

    const __half* Ap = A  + ((size_t)b * S_ + mt * TM) * S_;
    const __half* Bp = Bt + ((size_t)b * D_ + nt * TN) * S_;

    auto issue = [&](int c) {
        uint32_t sb = smb + (uint32_t)(c & 1) * STAGE2_B;
        const int ko = c * TK;
        load_tile(sb,         Ap + ko, S_, tid);
        load_tile(sb + BUF_B, Bp + ko, S_, tid);
        asm volatile("cp.async.commit_group;" ::: "memory");
    };

    float acc[4][4][4];
#pragma unroll
    for (int i = 0; i < 4; ++i)
#pragma unroll
        for (int n = 0; n < 4; ++n)
#pragma unroll
            for (int r = 0; r < 4; ++r) acc[i][n][r] = 0.f;

    issue(0);
    issue(1);

#pragma unroll 1
    for (int c = 0; c < NC; ++c) {
        if (c + 1 < NC) asm volatile("cp.async.wait_group 1;" ::: "memory");
        else            asm volatile("cp.async.wait_group 0;" ::: "memory");
        __syncthreads();

        const uint32_t sb = smb + (uint32_t)(c & 1) * STAGE2_B;
#pragma unroll
        for (int ks = 0; ks < 4; ++ks) {
            uint32_t ah[4][4], bh[2][4];
#pragma unroll
            for (int i = 0; i < 4; ++i) {
                int row = wm * 64 + i * 16 + lrow;
                uint32_t off = row * 128 + (((ks * 2 + lhalf) ^ (row & 7)) << 4);
                LDSM4(ah[i], sb + off);
            }
#pragma unroll
            for (int j = 0; j < 2; ++j) {
                int row = wn * 32 + j * 16 + lrow;
                uint32_t off = row * 128 + (((ks * 2 + lhalf) ^ (row & 7)) << 4);
                LDSM4(bh[j], sb + BUF_B + off);
            }
#pragma unroll
            for (int i = 0; i < 4; ++i)
#pragma unroll
                for (int n = 0; n < 4; ++n) {
                    int j = n >> 1, s = n & 1;
                    MMA_F16(acc[i][n], ah[i], bh[j][s], bh[j][s + 2]);
                }
        }
        __syncthreads();
        if (c + 2 < NC) issue(c + 2);
    }

    const int r0 = mt * TM + wm * 64 + (lane >> 2);
    const int cl0 = wn * 32 + (lane & 3) * 2;
#pragma unroll
    for (int i = 0; i < 4; ++i) {
#pragma unroll
        for (int n = 0; n < 4; ++n) {
            int col = nt * TN + cl0 + n * 8;
            size_t rowa = (size_t)(b * S_ + r0 + i * 16) * D_ + col;
            size_t rowb = rowa + (size_t)8 * D_;
            *reinterpret_cast<float2*>(Cp + rowa) =
                make_float2(acc[i][n][0], acc[i][n][1]);
            *reinterpret_cast<float2*>(Cp + rowb) =
                make_float2(acc[i][n][2], acc[i][n][3]);
        }
    }
}

// ------------------------------ softmax kernel ------------------------------
__global__ void __launch_bounds__(256) softmax_kernel() {
    __shared__ float red[8];
    const int r = blockIdx.x;                 // b*2048+q
    const int tid = threadIdx.x, lane = tid & 31, wid = tid >> 5;
    const float4* row4 = reinterpret_cast<const float4*>(g_s + (size_t)r * S_);
    float4 v0 = row4[tid], v1 = row4[tid + 256];

    float m = fmaxf(fmaxf(fmaxf(v0.x, v0.y), fmaxf(v0.z, v0.w)),
                    fmaxf(fmaxf(v1.x, v1.y), fmaxf(v1.z, v1.w)));
#pragma unroll
    for (int o = 16; o > 0; o >>= 1) m = fmaxf(m, __shfl_xor_sync(~0u, m, o));
    if (lane == 0) red[wid] = m;
    __syncthreads();
    m = red[0];
#pragma unroll
    for (int i = 1; i < 8; ++i) m = fmaxf(m, red[i]);
    __syncthreads();

    float e[8];
    e[0] = __expf(v0.x - m); e[1] = __expf(v0.y - m);
    e[2] = __expf(v0.z - m); e[3] = __expf(v0.w - m);
    e[4] = __expf(v1.x - m); e[5] = __expf(v1.y - m);
    e[6] = __expf(v1.z - m); e[7] = __expf(v1.w - m);
    float s = e[0] + e[1] + e[2] + e[3] + e[4] + e[5] + e[6] + e[7];
#pragma unroll
    for (int o = 16; o > 0; o >>= 1) s += __shfl_xor_sync(~0u, s, o);
    if (lane == 0) red[wid] = s;
    __syncthreads();
    s = red[0];
#pragma unroll
    for (int i = 1; i < 8; ++i) s += red[i];
    const float inv = 1.0f / s;

#pragma unroll
    for (int part = 0; part < 2; ++part) {
        size_t off = (size_t)r * S_ + (tid + part * 256) * 4;
        uint16_t h[4];
#pragma unroll
        for (int c = 0; c < 4; ++c)
            h[c] = __half_as_ushort(__float2half_rn(e[part * 4 + c] * inv));
        *reinterpret_cast<uint2*>(g_p + off) = pack4(h);
    }
}

// --------------------------------- launch -----------------------------------
extern "C" void kernel_launch(void* const* d_in, const int* in_sizes, int n_in,
                              void* d_out, int out_size) {
    const float* q    = (const float*)d_in[0];
    const float* k    = (const float*)d_in[1];
    const float* v    = (const float*)d_in[2];
    const float* mask = (const float*)d_in[3];
    float* out = (float*)d_out;

    cudaFuncSetAttribute(gemm1_kernel,
                         cudaFuncAttributeMaxDynamicSharedMemorySize, SMEM_G1);
    cudaFuncSetAttribute(gemm2_kernel,
                         cudaFuncAttributeMaxDynamicSharedMemorySize, SMEM_G2);

    __half *qh, *kh, *kl, *vt, *p;
    float* sbuf;
    cudaGetSymbolAddress((void**)&qh, g_qh);
    cudaGetSymbolAddress((void**)&kh, g_kh);
    cudaGetSymbolAddress((void**)&kl, g_kl);
    cudaGetSymbolAddress((void**)&vt, g_vt);
    cudaGetSymbolAddress((void**)&p,  g_p);
    cudaGetSymbolAddress((void**)&sbuf, g_s);

    conv_q_kernel<<<16384, 256>>>(q);
    conv_k_kernel<<<16384, 256>>>(k);
    conv_v_kernel<<<dim3(512, 8), 256>>>(v);

    gemm1_kernel<<<dim3(16, 16, 8), 256, SMEM_G1>>>(qh, kh, kl, mask, sbuf);
    softmax_kernel<<<16384, 256>>>();
    gemm2_kernel<<<dim3(16, 8, 8), 256, SMEM_G2>>>(p, vt, out);
}

// round 6
// speedup vs baseline: 10.3194x; 1.0524x over previous
#include <cuda_runtime.h>
#include <cuda_fp16.h>
#include <cstdint>

// ScaledDotProductAttention B=8, S=2048, D=1024 fp32.
// HMMA fp16: GEMM1 = 2-pass Qh*(Kh+Kl) with fused exp-epilogue (no softmax kernel),
// GEMM2 = single-pass fp16 with fused 1/rowsum normalization.

namespace {
constexpr int BN = 8, S_ = 2048, D_ = 1024;
constexpr float SCALE = 0.03125f;          // D^-0.5
constexpr float NEGV  = -1000000000.0f;

constexpr int TM = 128, TN = 128, TK = 64;
constexpr uint32_t BUF_B    = 16384;                      // one 128x64 fp16 tile
constexpr uint32_t STAGE1_B = 3 * BUF_B;                  // Ah,Bh,Bl
constexpr uint32_t SMEM_G1  = 2 * STAGE1_B + 1024 + 2048; // + mask row + rowsum buf
constexpr uint32_t STAGE2_B = 2 * BUF_B;                  // A,B
constexpr uint32_t SMEM_G2  = 2 * STAGE2_B + 512;         // + inv row buf
}  // namespace

// ------------------------- scratch (device globals) -------------------------
__device__ __align__(128) __half g_qh[(size_t)BN * S_ * D_];
__device__ __align__(128) __half g_kh[(size_t)BN * S_ * D_];
__device__ __align__(128) __half g_kl[(size_t)BN * S_ * D_];
__device__ __align__(128) __half g_vt[(size_t)BN * D_ * S_];   // V^T [b][d][s]
__device__ __align__(128) __half g_p [(size_t)BN * S_ * S_];   // unnormalized exp P~
__device__ __align__(128) float  g_ps[(size_t)BN * S_ * 16];   // row partial sums

// ------------------------------- helpers ------------------------------------
__device__ __forceinline__ uint32_t smem_u32(const void* p) {
    uint32_t a;
    asm("{ .reg .u64 t; cvta.to.shared.u64 t, %1; cvt.u32.u64 %0, t; }"
        : "=r"(a) : "l"(p));
    return a;
}

#define LDSM4(r, addr) \
    asm volatile("ldmatrix.sync.aligned.m8n8.x4.shared.b16 {%0,%1,%2,%3}, [%4];" \
        : "=r"((r)[0]), "=r"((r)[1]), "=r"((r)[2]), "=r"((r)[3]) : "r"(addr))

#define MMA_F16(d, a, b0, b1) \
    asm volatile("mma.sync.aligned.m16n8k16.row.col.f32.f16.f16.f32 " \
        "{%0,%1,%2,%3}, {%4,%5,%6,%7}, {%8,%9}, {%0,%1,%2,%3};" \
        : "+f"((d)[0]), "+f"((d)[1]), "+f"((d)[2]), "+f"((d)[3]) \
        : "r"((a)[0]), "r"((a)[1]), "r"((a)[2]), "r"((a)[3]), "r"(b0), "r"(b1))

__device__ __forceinline__ void split_f16(float x, uint16_t& h, uint16_t& l) {
    __half hb = __float2half_rn(x);
    __half lb = __float2half_rn(x - __half2float(hb));
    h = __half_as_ushort(hb);
    l = __half_as_ushort(lb);
}
__device__ __forceinline__ uint2 pack4(const uint16_t* h) {
    return make_uint2((uint32_t)h[0] | ((uint32_t)h[1] << 16),
                      (uint32_t)h[2] | ((uint32_t)h[3] << 16));
}

// --------------------------- convert kernels --------------------------------
__global__ void __launch_bounds__(256) conv_q_kernel(const float* __restrict__ src) {
    size_t e0 = ((size_t)blockIdx.x * 256 + threadIdx.x) * 4;
    float4 val = *reinterpret_cast<const float4*>(src + e0);
    uint16_t h[4];
    h[0] = __half_as_ushort(__float2half_rn(val.x));
    h[1] = __half_as_ushort(__float2half_rn(val.y));
    h[2] = __half_as_ushort(__float2half_rn(val.z));
    h[3] = __half_as_ushort(__float2half_rn(val.w));
    *reinterpret_cast<uint2*>(g_qh + e0) = pack4(h);
}

__global__ void __launch_bounds__(256) conv_k_kernel(const float* __restrict__ src) {
    size_t e0 = ((size_t)blockIdx.x * 256 + threadIdx.x) * 4;
    float4 val = *reinterpret_cast<const float4*>(src + e0);
    uint16_t h[4], l[4];
    split_f16(val.x, h[0], l[0]); split_f16(val.y, h[1], l[1]);
    split_f16(val.z, h[2], l[2]); split_f16(val.w, h[3], l[3]);
    *reinterpret_cast<uint2*>(g_kh + e0) = pack4(h);
    *reinterpret_cast<uint2*>(g_kl + e0) = pack4(l);
}

__global__ void __launch_bounds__(256) conv_v_kernel(const float* __restrict__ v) {
    __shared__ float tile[64][68];
    int b  = blockIdx.y;
    int st = blockIdx.x >> 4;
    int dt = blockIdx.x & 15;
    int tid = threadIdx.x;
    int i0 = tid >> 4, j4 = (tid & 15) * 4;
#pragma unroll
    for (int r = 0; r < 4; ++r) {
        int i = i0 + r * 16;
        float4 val = *reinterpret_cast<const float4*>(
            v + ((size_t)b * S_ + st * 64 + i) * D_ + dt * 64 + j4);
        tile[i][j4 + 0] = val.x; tile[i][j4 + 1] = val.y;
        tile[i][j4 + 2] = val.z; tile[i][j4 + 3] = val.w;
    }
    __syncthreads();
#pragma unroll
    for (int r = 0; r < 4; ++r) {
        int dl_ = i0 + r * 16;
        uint16_t h[4];
#pragma unroll
        for (int c = 0; c < 4; ++c)
            h[c] = __half_as_ushort(__float2half_rn(tile[j4 + c][dl_]));
        size_t off = ((size_t)b * D_ + dt * 64 + dl_) * S_ + st * 64 + j4;
        *reinterpret_cast<uint2*>(g_vt + off) = pack4(h);
    }
}

// ---------------------- shared cp.async tile loader -------------------------
__device__ __forceinline__ void load_tile(uint32_t dstbase, const __half* src,
                                          int ld, int tid) {
#pragma unroll
    for (int i = 0; i < 4; ++i) {
        int id = tid + i * 256;
        int row = id >> 3, cc = id & 7;
        uint32_t dst = dstbase + row * 128 + ((cc ^ (row & 7)) << 4);
        const __half* s = src + (size_t)row * ld + cc * 8;
        asm volatile("cp.async.cg.shared.global [%0], [%1], 16;"
                     :: "r"(dst), "l"(s));
    }
}

// ------------------ GEMM1: P~ = exp(QK^T*SCALE + mask) ----------------------
__global__ void __launch_bounds__(256, 2)
gemm1_kernel(const __half* __restrict__ Ah, const __half* __restrict__ Bh,
             const __half* __restrict__ Bl, const float* __restrict__ mask) {
    extern __shared__ __align__(1024) char smg[];
    const uint32_t smb = smem_u32(smg);
    float* smmask = (float*)(smg + 2 * STAGE1_B);
    float (*smsum)[4] = (float(*)[4])(smg + 2 * STAGE1_B + 1024);  // [128][4]

    const int tid = threadIdx.x;
    const int mt = blockIdx.x, nt = blockIdx.y, b = blockIdx.z;
    const int warp = tid >> 5, lane = tid & 31;
    const int wm = warp & 1, wn = warp >> 1;
    const int lrow = lane & 15, lhalf = lane >> 4;
    constexpr int NC = D_ / TK;  // 16

    const __half* Ahp = Ah + ((size_t)b * S_ + mt * TM) * D_;
    const __half* Bhp = Bh + ((size_t)b * S_ + nt * TN) * D_;
    const __half* Blp = Bl + ((size_t)b * S_ + nt * TN) * D_;

    if (tid < 128) smmask[tid] = mask[(size_t)b * S_ + nt * TN + tid] * NEGV;

    auto issue = [&](int c) {
        uint32_t sb = smb + (uint32_t)(c & 1) * STAGE1_B;
        const int ko = c * TK;
        load_tile(sb,             Ahp + ko, D_, tid);
        load_tile(sb + BUF_B,     Bhp + ko, D_, tid);
        load_tile(sb + 2 * BUF_B, Blp + ko, D_, tid);
        asm volatile("cp.async.commit_group;" ::: "memory");
    };

    float acc[4][4][4];
#pragma unroll
    for (int i = 0; i < 4; ++i)
#pragma unroll
        for (int n = 0; n < 4; ++n)
#pragma unroll
            for (int r = 0; r < 4; ++r) acc[i][n][r] = 0.f;

    issue(0);
    issue(1);

#pragma unroll 1
    for (int c = 0; c < NC; ++c) {
        if (c + 1 < NC) asm volatile("cp.async.wait_group 1;" ::: "memory");
        else            asm volatile("cp.async.wait_group 0;" ::: "memory");
        __syncthreads();

        const uint32_t sb = smb + (uint32_t)(c & 1) * STAGE1_B;
#pragma unroll
        for (int ks = 0; ks < 4; ++ks) {
            uint32_t ah[4][4], bh[2][4], bl[2][4];
#pragma unroll
            for (int i = 0; i < 4; ++i) {
                int row = wm * 64 + i * 16 + lrow;
                uint32_t off = row * 128 + (((ks * 2 + lhalf) ^ (row & 7)) << 4);
                LDSM4(ah[i], sb + off);
            }
#pragma unroll
            for (int j = 0; j < 2; ++j) {
                int row = wn * 32 + j * 16 + lrow;
                uint32_t off = row * 128 + (((ks * 2 + lhalf) ^ (row & 7)) << 4);
                LDSM4(bh[j], sb + BUF_B + off);
                LDSM4(bl[j], sb + 2 * BUF_B + off);
            }
#pragma unroll
            for (int i = 0; i < 4; ++i)
#pragma unroll
                for (int n = 0; n < 4; ++n) {
                    int j = n >> 1, s = n & 1;
                    MMA_F16(acc[i][n], ah[i], bh[j][s], bh[j][s + 2]);
                }
#pragma unroll
            for (int i = 0; i < 4; ++i)
#pragma unroll
                for (int n = 0; n < 4; ++n) {
                    int j = n >> 1, s = n & 1;
                    MMA_F16(acc[i][n], ah[i], bl[j][s], bl[j][s + 2]);
                }
        }
        __syncthreads();
        if (c + 2 < NC) issue(c + 2);
    }

    // ---- epilogue: e = exp(acc*SCALE + mask), write fp16, reduce row sums ----
    const int rloc = wm * 64 + (lane >> 2);       // local row (lo half)
    const int r0 = mt * TM + rloc;                // global row within batch
    const int cl0 = wn * 32 + (lane & 3) * 2;
#pragma unroll
    for (int i = 0; i < 4; ++i) {
        float sum_lo = 0.f, sum_hi = 0.f;
#pragma unroll
        for (int n = 0; n < 4; ++n) {
            int cl = cl0 + n * 8;
            float mk0 = smmask[cl], mk1 = smmask[cl + 1];
            float e0 = __expf(acc[i][n][0] * SCALE + mk0);
            float e1 = __expf(acc[i][n][1] * SCALE + mk1);
            float e2 = __expf(acc[i][n][2] * SCALE + mk0);
            float e3 = __expf(acc[i][n][3] * SCALE + mk1);
            sum_lo += e0 + e1;
            sum_hi += e2 + e3;
            size_t rowa = (size_t)(b * S_ + r0 + i * 16) * S_ + nt * TN + cl;
            size_t rowb = rowa + (size_t)8 * S_;
            *reinterpret_cast<__half2*>(g_p + rowa) =
                __floats2half2_rn(e0, e1);
            *reinterpret_cast<__half2*>(g_p + rowb) =
                __floats2half2_rn(e2, e3);
        }
        // reduce over the 4 lanes of the quad (same row)
#pragma unroll
        for (int o = 1; o < 4; o <<= 1) {
            sum_lo += __shfl_xor_sync(~0u, sum_lo, o);
            sum_hi += __shfl_xor_sync(~0u, sum_hi, o);
        }
        if ((lane & 3) == 0) {
            smsum[rloc + i * 16][wn]     = sum_lo;
            smsum[rloc + i * 16 + 8][wn] = sum_hi;
        }
    }
    __syncthreads();
    if (tid < 128) {
        float s = smsum[tid][0] + smsum[tid][1] + smsum[tid][2] + smsum[tid][3];
        g_ps[((size_t)(b * S_ + mt * TM + tid)) * 16 + nt] = s;
    }
}

// ------------- GEMM2: out = (P~ @ V) * (1/rowsum)  (1-pass fp16) -------------
__global__ void __launch_bounds__(256, 2)
gemm2_kernel(const __half* __restrict__ A, const __half* __restrict__ Bt,
             float* __restrict__ Cp) {
    extern __shared__ __align__(1024) char smg[];
    const uint32_t smb = smem_u32(smg);
    float* sminv = (float*)(smg + 2 * STAGE2_B);  // [128]

    const int tid = threadIdx.x;
    const int mt = blockIdx.x, nt = blockIdx.y, b = blockIdx.z;
    const int warp = tid >> 5, lane = tid & 31;
    const int wm = warp & 1, wn = warp >> 1;
    const int lrow = lane & 15, lhalf = lane >> 4;
    constexpr int NC = S_ / TK;  // 32

    const __half* Ap = A  + ((size_t)b * S_ + mt * TM) * S_;
    const __half* Bp = Bt + ((size_t)b * D_ + nt * TN) * S_;

    // per-row 1/sum from the 16 deterministic partials
    if (tid < 128) {
        const float* ps = g_ps + ((size_t)(b * S_ + mt * TM + tid)) * 16;
        float s = 0.f;
#pragma unroll
        for (int j = 0; j < 16; ++j) s += ps[j];
        sminv[tid] = 1.0f / s;
    }

    auto issue = [&](int c) {
        uint32_t sb = smb + (uint32_t)(c & 1) * STAGE2_B;
        const int ko = c * TK;
        load_tile(sb,         Ap + ko, S_, tid);
        load_tile(sb + BUF_B, Bp + ko, S_, tid);
        asm volatile("cp.async.commit_group;" ::: "memory");
    };

    float acc[4][4][4];
#pragma unroll
    for (int i = 0; i < 4; ++i)
#pragma unroll
        for (int n = 0; n < 4; ++n)
#pragma unroll
            for (int r = 0; r < 4; ++r) acc[i][n][r] = 0.f;

    issue(0);
    issue(1);

#pragma unroll 1
    for (int c = 0; c < NC; ++c) {
        if (c + 1 < NC) asm volatile("cp.async.wait_group 1;" ::: "memory");
        else            asm volatile("cp.async.wait_group 0;" ::: "memory");
        __syncthreads();

        const uint32_t sb = smb + (uint32_t)(c & 1) * STAGE2_B;
#pragma unroll
        for (int ks = 0; ks < 4; ++ks) {
            uint32_t ah[4][4], bh[2][4];
#pragma unroll
            for (int i = 0; i < 4; ++i) {
                int row = wm * 64 + i * 16 + lrow;
                uint32_t off = row * 128 + (((ks * 2 + lhalf) ^ (row & 7)) << 4);
                LDSM4(ah[i], sb + off);
            }
#pragma unroll
            for (int j = 0; j < 2; ++j) {
                int row = wn * 32 + j * 16 + lrow;
                uint32_t off = row * 128 + (((ks * 2 + lhalf) ^ (row & 7)) << 4);
                LDSM4(bh[j], sb + BUF_B + off);
            }
#pragma unroll
            for (int i = 0; i < 4; ++i)
#pragma unroll
                for (int n = 0; n < 4; ++n) {
                    int j = n >> 1, s = n & 1;
                    MMA_F16(acc[i][n], ah[i], bh[j][s], bh[j][s + 2]);
                }
        }
        __syncthreads();
        if (c + 2 < NC) issue(c + 2);
    }

    const int rloc = wm * 64 + (lane >> 2);
    const int r0 = mt * TM + rloc;
    const int cl0 = wn * 32 + (lane & 3) * 2;
#pragma unroll
    for (int i = 0; i < 4; ++i) {
        float inv_lo = sminv[rloc + i * 16];
        float inv_hi = sminv[rloc + i * 16 + 8];
#pragma unroll
        for (int n = 0; n < 4; ++n) {
            int col = nt * TN + cl0 + n * 8;
            size_t rowa = (size_t)(b * S_ + r0 + i * 16) * D_ + col;
            size_t rowb = rowa + (size_t)8 * D_;
            *reinterpret_cast<float2*>(Cp + rowa) =
                make_float2(acc[i][n][0] * inv_lo, acc[i][n][1] * inv_lo);
            *reinterpret_cast<float2*>(Cp + rowb) =
                make_float2(acc[i][n][2] * inv_hi, acc[i][n][3] * inv_hi);
        }
    }
}

// --------------------------------- launch -----------------------------------
extern "C" void kernel_launch(void* const* d_in, const int* in_sizes, int n_in,
                              void* d_out, int out_size) {
    const float* q    = (const float*)d_in[0];
    const float* k    = (const float*)d_in[1];
    const float* v    = (const float*)d_in[2];
    const float* mask = (const float*)d_in[3];
    float* out = (float*)d_out;

    cudaFuncSetAttribute(gemm1_kernel,
                         cudaFuncAttributeMaxDynamicSharedMemorySize, SMEM_G1);
    cudaFuncSetAttribute(gemm2_kernel,
                         cudaFuncAttributeMaxDynamicSharedMemorySize, SMEM_G2);

    __half *qh, *kh, *kl, *vt, *p;
    cudaGetSymbolAddress((void**)&qh, g_qh);
    cudaGetSymbolAddress((void**)&kh, g_kh);
    cudaGetSymbolAddress((void**)&kl, g_kl);
    cudaGetSymbolAddress((void**)&vt, g_vt);
    cudaGetSymbolAddress((void**)&p,  g_p);

    conv_q_kernel<<<16384, 256>>>(q);
    conv_k_kernel<<<16384, 256>>>(k);
    conv_v_kernel<<<dim3(512, 8), 256>>>(v);

    gemm1_kernel<<<dim3(16, 16, 8), 256, SMEM_G1>>>(qh, kh, kl, mask);
    gemm2_kernel<<<dim3(16, 8, 8), 256, SMEM_G2>>>(p, vt, out);
}

// round 7
// speedup vs baseline: 13.7259x; 1.3301x over previous
#include <cuda_runtime.h>
#include <cuda_fp16.h>
#include <cstdint>

// ScaledDotProductAttention B=8, S=2048, D=1024 fp32.
// HMMA fp16 1-pass both GEMMs; fused exp epilogue + fused 1/rowsum normalization.

namespace {
constexpr int BN = 8, S_ = 2048, D_ = 1024;
constexpr float SCALE = 0.03125f;          // D^-0.5
constexpr float NEGV  = -1000000000.0f;

constexpr int TM = 128, TN = 128, TK = 64;
constexpr uint32_t BUF_B   = 16384;                      // one 128x64 fp16 tile
constexpr uint32_t STAGE_B = 2 * BUF_B;                  // A,B
constexpr uint32_t SMEM_G1 = 2 * STAGE_B + 1024 + 2048;  // + mask row + rowsum buf
constexpr uint32_t SMEM_G2 = 2 * STAGE_B + 512;          // + inv row buf
}  // namespace

// ------------------------- scratch (device globals) -------------------------
__device__ __align__(128) __half g_qh[(size_t)BN * S_ * D_];
__device__ __align__(128) __half g_kh[(size_t)BN * S_ * D_];
__device__ __align__(128) __half g_vt[(size_t)BN * D_ * S_];   // V^T [b][d][s]
__device__ __align__(128) __half g_p [(size_t)BN * S_ * S_];   // unnormalized exp P~
__device__ __align__(128) float  g_ps[(size_t)BN * S_ * 16];   // row partial sums

// ------------------------------- helpers ------------------------------------
__device__ __forceinline__ uint32_t smem_u32(const void* p) {
    uint32_t a;
    asm("{ .reg .u64 t; cvta.to.shared.u64 t, %1; cvt.u32.u64 %0, t; }"
        : "=r"(a) : "l"(p));
    return a;
}

#define LDSM4(r, addr) \
    asm volatile("ldmatrix.sync.aligned.m8n8.x4.shared.b16 {%0,%1,%2,%3}, [%4];" \
        : "=r"((r)[0]), "=r"((r)[1]), "=r"((r)[2]), "=r"((r)[3]) : "r"(addr))

#define MMA_F16(d, a, b0, b1) \
    asm volatile("mma.sync.aligned.m16n8k16.row.col.f32.f16.f16.f32 " \
        "{%0,%1,%2,%3}, {%4,%5,%6,%7}, {%8,%9}, {%0,%1,%2,%3};" \
        : "+f"((d)[0]), "+f"((d)[1]), "+f"((d)[2]), "+f"((d)[3]) \
        : "r"((a)[0]), "r"((a)[1]), "r"((a)[2]), "r"((a)[3]), "r"(b0), "r"(b1))

__device__ __forceinline__ uint2 pack4(const uint16_t* h) {
    return make_uint2((uint32_t)h[0] | ((uint32_t)h[1] << 16),
                      (uint32_t)h[2] | ((uint32_t)h[3] << 16));
}

// --------------------------- convert kernels --------------------------------
__global__ void __launch_bounds__(256) conv_h_kernel(
    const float* __restrict__ src, __half* __restrict__ dst) {
    size_t e0 = ((size_t)blockIdx.x * 256 + threadIdx.x) * 4;
    float4 val = *reinterpret_cast<const float4*>(src + e0);
    uint16_t h[4];
    h[0] = __half_as_ushort(__float2half_rn(val.x));
    h[1] = __half_as_ushort(__float2half_rn(val.y));
    h[2] = __half_as_ushort(__float2half_rn(val.z));
    h[3] = __half_as_ushort(__float2half_rn(val.w));
    *reinterpret_cast<uint2*>(dst + e0) = pack4(h);
}

__global__ void __launch_bounds__(256) conv_v_kernel(const float* __restrict__ v) {
    __shared__ float tile[64][68];
    int b  = blockIdx.y;
    int st = blockIdx.x >> 4;
    int dt = blockIdx.x & 15;
    int tid = threadIdx.x;
    int i0 = tid >> 4, j4 = (tid & 15) * 4;
#pragma unroll
    for (int r = 0; r < 4; ++r) {
        int i = i0 + r * 16;
        float4 val = *reinterpret_cast<const float4*>(
            v + ((size_t)b * S_ + st * 64 + i) * D_ + dt * 64 + j4);
        tile[i][j4 + 0] = val.x; tile[i][j4 + 1] = val.y;
        tile[i][j4 + 2] = val.z; tile[i][j4 + 3] = val.w;
    }
    __syncthreads();
#pragma unroll
    for (int r = 0; r < 4; ++r) {
        int dl_ = i0 + r * 16;
        uint16_t h[4];
#pragma unroll
        for (int c = 0; c < 4; ++c)
            h[c] = __half_as_ushort(__float2half_rn(tile[j4 + c][dl_]));
        size_t off = ((size_t)b * D_ + dt * 64 + dl_) * S_ + st * 64 + j4;
        *reinterpret_cast<uint2*>(g_vt + off) = pack4(h);
    }
}

// ---------------------- shared cp.async tile loader -------------------------
__device__ __forceinline__ void load_tile(uint32_t dstbase, const __half* src,
                                          int ld, int tid) {
#pragma unroll
    for (int i = 0; i < 4; ++i) {
        int id = tid + i * 256;
        int row = id >> 3, cc = id & 7;
        uint32_t dst = dstbase + row * 128 + ((cc ^ (row & 7)) << 4);
        const __half* s = src + (size_t)row * ld + cc * 8;
        asm volatile("cp.async.cg.shared.global [%0], [%1], 16;"
                     :: "r"(dst), "l"(s));
    }
}

// ------------------ GEMM1: P~ = exp(QK^T*SCALE + mask) ----------------------
__global__ void __launch_bounds__(256, 2)
gemm1_kernel(const __half* __restrict__ Ah, const __half* __restrict__ Bh,
             const float* __restrict__ mask) {
    extern __shared__ __align__(1024) char smg[];
    const uint32_t smb = smem_u32(smg);
    float* smmask = (float*)(smg + 2 * STAGE_B);
    float (*smsum)[4] = (float(*)[4])(smg + 2 * STAGE_B + 1024);  // [128][4]

    const int tid = threadIdx.x;
    const int mt = blockIdx.x, nt = blockIdx.y, b = blockIdx.z;
    const int warp = tid >> 5, lane = tid & 31;
    const int wm = warp & 1, wn = warp >> 1;
    const int lrow = lane & 15, lhalf = lane >> 4;
    constexpr int NC = D_ / TK;  // 16

    const __half* Ahp = Ah + ((size_t)b * S_ + mt * TM) * D_;
    const __half* Bhp = Bh + ((size_t)b * S_ + nt * TN) * D_;

    if (tid < 128) smmask[tid] = mask[(size_t)b * S_ + nt * TN + tid] * NEGV;

    auto issue = [&](int c) {
        uint32_t sb = smb + (uint32_t)(c & 1) * STAGE_B;
        const int ko = c * TK;
        load_tile(sb,         Ahp + ko, D_, tid);
        load_tile(sb + BUF_B, Bhp + ko, D_, tid);
        asm volatile("cp.async.commit_group;" ::: "memory");
    };

    float acc[4][4][4];
#pragma unroll
    for (int i = 0; i < 4; ++i)
#pragma unroll
        for (int n = 0; n < 4; ++n)
#pragma unroll
            for (int r = 0; r < 4; ++r) acc[i][n][r] = 0.f;

    issue(0);
    issue(1);

#pragma unroll 1
    for (int c = 0; c < NC; ++c) {
        if (c + 1 < NC) asm volatile("cp.async.wait_group 1;" ::: "memory");
        else            asm volatile("cp.async.wait_group 0;" ::: "memory");
        __syncthreads();

        const uint32_t sb = smb + (uint32_t)(c & 1) * STAGE_B;
#pragma unroll
        for (int ks = 0; ks < 4; ++ks) {
            uint32_t ah[4][4], bh[2][4];
#pragma unroll
            for (int i = 0; i < 4; ++i) {
                int row = wm * 64 + i * 16 + lrow;
                uint32_t off = row * 128 + (((ks * 2 + lhalf) ^ (row & 7)) << 4);
                LDSM4(ah[i], sb + off);
            }
#pragma unroll
            for (int j = 0; j < 2; ++j) {
                int row = wn * 32 + j * 16 + lrow;
                uint32_t off = row * 128 + (((ks * 2 + lhalf) ^ (row & 7)) << 4);
                LDSM4(bh[j], sb + BUF_B + off);
            }
#pragma unroll
            for (int i = 0; i < 4; ++i)
#pragma unroll
                for (int n = 0; n < 4; ++n) {
                    int j = n >> 1, s = n & 1;
                    MMA_F16(acc[i][n], ah[i], bh[j][s], bh[j][s + 2]);
                }
        }
        __syncthreads();
        if (c + 2 < NC) issue(c + 2);
    }

    // ---- epilogue: e = exp(acc*SCALE + mask), write fp16, reduce row sums ----
    const int rloc = wm * 64 + (lane >> 2);
    const int r0 = mt * TM + rloc;
    const int cl0 = wn * 32 + (lane & 3) * 2;
#pragma unroll
    for (int i = 0; i < 4; ++i) {
        float sum_lo = 0.f, sum_hi = 0.f;
#pragma unroll
        for (int n = 0; n < 4; ++n) {
            int cl = cl0 + n * 8;
            float mk0 = smmask[cl], mk1 = smmask[cl + 1];
            float e0 = __expf(acc[i][n][0] * SCALE + mk0);
            float e1 = __expf(acc[i][n][1] * SCALE + mk1);
            float e2 = __expf(acc[i][n][2] * SCALE + mk0);
            float e3 = __expf(acc[i][n][3] * SCALE + mk1);
            sum_lo += e0 + e1;
            sum_hi += e2 + e3;
            size_t rowa = (size_t)(b * S_ + r0 + i * 16) * S_ + nt * TN + cl;
            size_t rowb = rowa + (size_t)8 * S_;
            *reinterpret_cast<__half2*>(g_p + rowa) = __floats2half2_rn(e0, e1);
            *reinterpret_cast<__half2*>(g_p + rowb) = __floats2half2_rn(e2, e3);
        }
#pragma unroll
        for (int o = 1; o < 4; o <<= 1) {
            sum_lo += __shfl_xor_sync(~0u, sum_lo, o);
            sum_hi += __shfl_xor_sync(~0u, sum_hi, o);
        }
        if ((lane & 3) == 0) {
            smsum[rloc + i * 16][wn]     = sum_lo;
            smsum[rloc + i * 16 + 8][wn] = sum_hi;
        }
    }
    __syncthreads();
    if (tid < 128) {
        float s = smsum[tid][0] + smsum[tid][1] + smsum[tid][2] + smsum[tid][3];
        g_ps[((size_t)(b * S_ + mt * TM + tid)) * 16 + nt] = s;
    }
}

// ------------- GEMM2: out = (P~ @ V) * (1/rowsum)  (1-pass fp16) -------------
__global__ void __launch_bounds__(256, 2)
gemm2_kernel(const __half* __restrict__ A, const __half* __restrict__ Bt,
             float* __restrict__ Cp) {
    extern __shared__ __align__(1024) char smg[];
    const uint32_t smb = smem_u32(smg);
    float* sminv = (float*)(smg + 2 * STAGE_B);  // [128]

    const int tid = threadIdx.x;
    const int mt = blockIdx.x, nt = blockIdx.y, b = blockIdx.z;
    const int warp = tid >> 5, lane = tid & 31;
    const int wm = warp & 1, wn = warp >> 1;
    const int lrow = lane & 15, lhalf = lane >> 4;
    constexpr int NC = S_ / TK;  // 32

    const __half* Ap = A  + ((size_t)b * S_ + mt * TM) * S_;
    const __half* Bp = Bt + ((size_t)b * D_ + nt * TN) * S_;

    if (tid < 128) {
        const float* ps = g_ps + ((size_t)(b * S_ + mt * TM + tid)) * 16;
        float s = 0.f;
#pragma unroll
        for (int j = 0; j < 16; ++j) s += ps[j];
        sminv[tid] = 1.0f / s;
    }

    auto issue = [&](int c) {
        uint32_t sb = smb + (uint32_t)(c & 1) * STAGE_B;
        const int ko = c * TK;
        load_tile(sb,         Ap + ko, S_, tid);
        load_tile(sb + BUF_B, Bp + ko, S_, tid);
        asm volatile("cp.async.commit_group;" ::: "memory");
    };

    float acc[4][4][4];
#pragma unroll
    for (int i = 0; i < 4; ++i)
#pragma unroll
        for (int n = 0; n < 4; ++n)
#pragma unroll
            for (int r = 0; r < 4; ++r) acc[i][n][r] = 0.f;

    issue(0);
    issue(1);

#pragma unroll 1
    for (int c = 0; c < NC; ++c) {
        if (c + 1 < NC) asm volatile("cp.async.wait_group 1;" ::: "memory");
        else            asm volatile("cp.async.wait_group 0;" ::: "memory");
        __syncthreads();

        const uint32_t sb = smb + (uint32_t)(c & 1) * STAGE_B;
#pragma unroll
        for (int ks = 0; ks < 4; ++ks) {
            uint32_t ah[4][4], bh[2][4];
#pragma unroll
            for (int i = 0; i < 4; ++i) {
                int row = wm * 64 + i * 16 + lrow;
                uint32_t off = row * 128 + (((ks * 2 + lhalf) ^ (row & 7)) << 4);
                LDSM4(ah[i], sb + off);
            }
#pragma unroll
            for (int j = 0; j < 2; ++j) {
                int row = wn * 32 + j * 16 + lrow;
                uint32_t off = row * 128 + (((ks * 2 + lhalf) ^ (row & 7)) << 4);
                LDSM4(bh[j], sb + BUF_B + off);
            }
#pragma unroll
            for (int i = 0; i < 4; ++i)
#pragma unroll
                for (int n = 0; n < 4; ++n) {
                    int j = n >> 1, s = n & 1;
                    MMA_F16(acc[i][n], ah[i], bh[j][s], bh[j][s + 2]);
                }
        }
        __syncthreads();
        if (c + 2 < NC) issue(c + 2);
    }

    const int rloc = wm * 64 + (lane >> 2);
    const int r0 = mt * TM + rloc;
    const int cl0 = wn * 32 + (lane & 3) * 2;
#pragma unroll
    for (int i = 0; i < 4; ++i) {
        float inv_lo = sminv[rloc + i * 16];
        float inv_hi = sminv[rloc + i * 16 + 8];
#pragma unroll
        for (int n = 0; n < 4; ++n) {
            int col = nt * TN + cl0 + n * 8;
            size_t rowa = (size_t)(b * S_ + r0 + i * 16) * D_ + col;
            size_t rowb = rowa + (size_t)8 * D_;
            *reinterpret_cast<float2*>(Cp + rowa) =
                make_float2(acc[i][n][0] * inv_lo, acc[i][n][1] * inv_lo);
            *reinterpret_cast<float2*>(Cp + rowb) =
                make_float2(acc[i][n][2] * inv_hi, acc[i][n][3] * inv_hi);
        }
    }
}

// --------------------------------- launch -----------------------------------
extern "C" void kernel_launch(void* const* d_in, const int* in_sizes, int n_in,
                              void* d_out, int out_size) {
    const float* q    = (const float*)d_in[0];
    const float* k    = (const float*)d_in[1];
    const float* v    = (const float*)d_in[2];
    const float* mask = (const float*)d_in[3];
    float* out = (float*)d_out;

    cudaFuncSetAttribute(gemm1_kernel,
                         cudaFuncAttributeMaxDynamicSharedMemorySize, SMEM_G1);
    cudaFuncSetAttribute(gemm2_kernel,
                         cudaFuncAttributeMaxDynamicSharedMemorySize, SMEM_G2);

    __half *qh, *kh, *vt, *p;
    cudaGetSymbolAddress((void**)&qh, g_qh);
    cudaGetSymbolAddress((void**)&kh, g_kh);
    cudaGetSymbolAddress((void**)&vt, g_vt);
    cudaGetSymbolAddress((void**)&p,  g_p);

    conv_h_kernel<<<16384, 256>>>(q, qh);
    conv_h_kernel<<<16384, 256>>>(k, kh);
    conv_v_kernel<<<dim3(512, 8), 256>>>(v);

    gemm1_kernel<<<dim3(16, 16, 8), 256, SMEM_G1>>>(qh, kh, mask);
    gemm2_kernel<<<dim3(16, 8, 8), 256, SMEM_G2>>>(p, vt, out);
}

// round 8
// speedup vs baseline: 13.9529x; 1.0165x over previous
#include <cuda_runtime.h>
#include <cuda_fp16.h>
#include <cstdint>

// ScaledDotProductAttention B=8, S=2048, D=1024 fp32.
// HMMA fp16 1-pass both GEMMs; fused exp epilogue + fused 1/rowsum normalization.
// R8: 3-stage cp.async pipeline, single barrier/chunk, strength-reduced addressing.

namespace {
constexpr int BN = 8, S_ = 2048, D_ = 1024;
constexpr float SCALE = 0.03125f;          // D^-0.5
constexpr float NEGV  = -1000000000.0f;

constexpr int TM = 128, TN = 128, TK = 64;
constexpr uint32_t BUF_B   = 16384;                      // one 128x64 fp16 tile
constexpr uint32_t STAGE_B = 2 * BUF_B;                  // A,B
constexpr uint32_t PIPE_B  = 3 * STAGE_B;                // 98304
constexpr uint32_t SMEM_G1 = PIPE_B + 1024 + 2048;       // + mask row + rowsum buf
constexpr uint32_t SMEM_G2 = PIPE_B + 512;               // + inv row buf
}  // namespace

// ------------------------- scratch (device globals) -------------------------
__device__ __align__(128) __half g_qh[(size_t)BN * S_ * D_];
__device__ __align__(128) __half g_kh[(size_t)BN * S_ * D_];
__device__ __align__(128) __half g_vt[(size_t)BN * D_ * S_];   // V^T [b][d][s]
__device__ __align__(128) __half g_p [(size_t)BN * S_ * S_];   // unnormalized exp P~
__device__ __align__(128) float  g_ps[(size_t)BN * S_ * 16];   // row partial sums

// ------------------------------- helpers ------------------------------------
__device__ __forceinline__ uint32_t smem_u32(const void* p) {
    uint32_t a;
    asm("{ .reg .u64 t; cvta.to.shared.u64 t, %1; cvt.u32.u64 %0, t; }"
        : "=r"(a) : "l"(p));
    return a;
}

#define LDSM4(r, addr) \
    asm volatile("ldmatrix.sync.aligned.m8n8.x4.shared.b16 {%0,%1,%2,%3}, [%4];" \
        : "=r"((r)[0]), "=r"((r)[1]), "=r"((r)[2]), "=r"((r)[3]) : "r"(addr))

#define MMA_F16(d, a, b0, b1) \
    asm volatile("mma.sync.aligned.m16n8k16.row.col.f32.f16.f16.f32 " \
        "{%0,%1,%2,%3}, {%4,%5,%6,%7}, {%8,%9}, {%0,%1,%2,%3};" \
        : "+f"((d)[0]), "+f"((d)[1]), "+f"((d)[2]), "+f"((d)[3]) \
        : "r"((a)[0]), "r"((a)[1]), "r"((a)[2]), "r"((a)[3]), "r"(b0), "r"(b1))

#define CP_ASYNC16(dst, src) \
    asm volatile("cp.async.cg.shared.global [%0], [%1], 16;" :: "r"(dst), "l"(src))
#define CP_COMMIT()  asm volatile("cp.async.commit_group;" ::: "memory")
#define CP_WAIT(n)   asm volatile("cp.async.wait_group %0;" :: "n"(n) : "memory")

__device__ __forceinline__ uint2 pack4(const uint16_t* h) {
    return make_uint2((uint32_t)h[0] | ((uint32_t)h[1] << 16),
                      (uint32_t)h[2] | ((uint32_t)h[3] << 16));
}

// --------------------------- convert kernels --------------------------------
__global__ void __launch_bounds__(256) conv_h_kernel(
    const float* __restrict__ src, __half* __restrict__ dst) {
    size_t e0 = ((size_t)blockIdx.x * 256 + threadIdx.x) * 4;
    float4 val = *reinterpret_cast<const float4*>(src + e0);
    uint16_t h[4];
    h[0] = __half_as_ushort(__float2half_rn(val.x));
    h[1] = __half_as_ushort(__float2half_rn(val.y));
    h[2] = __half_as_ushort(__float2half_rn(val.z));
    h[3] = __half_as_ushort(__float2half_rn(val.w));
    *reinterpret_cast<uint2*>(dst + e0) = pack4(h);
}

__global__ void __launch_bounds__(256) conv_v_kernel(const float* __restrict__ v) {
    __shared__ float tile[64][68];
    int b  = blockIdx.y;
    int st = blockIdx.x >> 4;
    int dt = blockIdx.x & 15;
    int tid = threadIdx.x;
    int i0 = tid >> 4, j4 = (tid & 15) * 4;
#pragma unroll
    for (int r = 0; r < 4; ++r) {
        int i = i0 + r * 16;
        float4 val = *reinterpret_cast<const float4*>(
            v + ((size_t)b * S_ + st * 64 + i) * D_ + dt * 64 + j4);
        tile[i][j4 + 0] = val.x; tile[i][j4 + 1] = val.y;
        tile[i][j4 + 2] = val.z; tile[i][j4 + 3] = val.w;
    }
    __syncthreads();
#pragma unroll
    for (int r = 0; r < 4; ++r) {
        int dl_ = i0 + r * 16;
        uint16_t h[4];
#pragma unroll
        for (int c = 0; c < 4; ++c)
            h[c] = __half_as_ushort(__float2half_rn(tile[j4 + c][dl_]));
        size_t off = ((size_t)b * D_ + dt * 64 + dl_) * S_ + st * 64 + j4;
        *reinterpret_cast<uint2*>(g_vt + off) = pack4(h);
    }
}

// ------------------ GEMM1: P~ = exp(QK^T*SCALE + mask) ----------------------
__global__ void __launch_bounds__(256, 2)
gemm1_kernel(const __half* __restrict__ Ah, const __half* __restrict__ Bh,
             const float* __restrict__ mask) {
    extern __shared__ __align__(1024) char smg[];
    const uint32_t smb = smem_u32(smg);
    float* smmask = (float*)(smg + PIPE_B);
    float (*smsum)[4] = (float(*)[4])(smg + PIPE_B + 1024);  // [128][4]

    const int tid = threadIdx.x;
    const int mt = blockIdx.x, nt = blockIdx.y, b = blockIdx.z;
    const int warp = tid >> 5, lane = tid & 31;
    const int wm = warp & 1, wn = warp >> 1;
    const int lrow = lane & 15;
    const int lh16 = (lane >> 4) << 4;
    const int r7 = (lane & 7) << 4;
    constexpr int NC = D_ / TK;  // 16

    // cp.async: per-thread running gmem pointers + fixed smem dst offsets
    const int drow = tid >> 3, cc = tid & 7;
    const uint32_t dstoff0 = (uint32_t)(drow * 128 + ((cc ^ (drow & 7)) << 4));
    const __half* gA = Ah + ((size_t)b * S_ + mt * TM + drow) * D_ + cc * 8;
    const __half* gB = Bh + ((size_t)b * S_ + nt * TN + drow) * D_ + cc * 8;

    if (tid < 128) smmask[tid] = mask[(size_t)b * S_ + nt * TN + tid] * NEGV;

    uint32_t sload = 0;
    auto issue = [&]() {
        uint32_t da = smb + sload + dstoff0;
#pragma unroll
        for (int i = 0; i < 4; ++i) {
            CP_ASYNC16(da + i * 4096,         gA + i * 32 * D_);
            CP_ASYNC16(da + BUF_B + i * 4096, gB + i * 32 * D_);
        }
        CP_COMMIT();
        gA += TK; gB += TK;
        sload += STAGE_B; if (sload == PIPE_B) sload = 0;
    };

    float acc[4][4][4];
#pragma unroll
    for (int i = 0; i < 4; ++i)
#pragma unroll
        for (int n = 0; n < 4; ++n)
#pragma unroll
            for (int r = 0; r < 4; ++r) acc[i][n][r] = 0.f;

    issue();
    issue();

    // LDSM per-warp base offsets (within a stage)
    const uint32_t cA = (uint32_t)((wm * 64 + lrow) * 128);
    const uint32_t cB = (uint32_t)(BUF_B + (wn * 32 + lrow) * 128);

    uint32_t scomp = 0;
#pragma unroll 1
    for (int c = 0; c < NC; ++c) {
        if (c + 1 < NC) CP_WAIT(1);
        else            CP_WAIT(0);
        __syncthreads();
        if (c + 2 < NC) issue();

        const uint32_t uA0 = smb + scomp + cA;
        const uint32_t uB0 = smb + scomp + cB;
        scomp += STAGE_B; if (scomp == PIPE_B) scomp = 0;

#pragma unroll
        for (int ks = 0; ks < 4; ++ks) {
            const uint32_t kxr = (uint32_t)((ks * 32 + lh16) ^ r7);
            uint32_t ah[4][4], bh[2][4];
#pragma unroll
            for (int i = 0; i < 4; ++i) LDSM4(ah[i], uA0 + i * 2048 + kxr);
#pragma unroll
            for (int j = 0; j < 2; ++j) LDSM4(bh[j], uB0 + j * 2048 + kxr);
#pragma unroll
            for (int i = 0; i < 4; ++i)
#pragma unroll
                for (int n = 0; n < 4; ++n) {
                    int j = n >> 1, s = n & 1;
                    MMA_F16(acc[i][n], ah[i], bh[j][s], bh[j][s + 2]);
                }
        }
    }

    // ---- epilogue: e = exp(acc*SCALE + mask), write fp16, reduce row sums ----
    const int rloc = wm * 64 + (lane >> 2);
    const int r0 = mt * TM + rloc;
    const int cl0 = wn * 32 + (lane & 3) * 2;
#pragma unroll
    for (int i = 0; i < 4; ++i) {
        float sum_lo = 0.f, sum_hi = 0.f;
#pragma unroll
        for (int n = 0; n < 4; ++n) {
            int cl = cl0 + n * 8;
            float mk0 = smmask[cl], mk1 = smmask[cl + 1];
            float e0 = __expf(acc[i][n][0] * SCALE + mk0);
            float e1 = __expf(acc[i][n][1] * SCALE + mk1);
            float e2 = __expf(acc[i][n][2] * SCALE + mk0);
            float e3 = __expf(acc[i][n][3] * SCALE + mk1);
            sum_lo += e0 + e1;
            sum_hi += e2 + e3;
            size_t rowa = (size_t)(b * S_ + r0 + i * 16) * S_ + nt * TN + cl;
            size_t rowb = rowa + (size_t)8 * S_;
            *reinterpret_cast<__half2*>(g_p + rowa) = __floats2half2_rn(e0, e1);
            *reinterpret_cast<__half2*>(g_p + rowb) = __floats2half2_rn(e2, e3);
        }
#pragma unroll
        for (int o = 1; o < 4; o <<= 1) {
            sum_lo += __shfl_xor_sync(~0u, sum_lo, o);
            sum_hi += __shfl_xor_sync(~0u, sum_hi, o);
        }
        if ((lane & 3) == 0) {
            smsum[rloc + i * 16][wn]     = sum_lo;
            smsum[rloc + i * 16 + 8][wn] = sum_hi;
        }
    }
    __syncthreads();
    if (tid < 128) {
        float s = smsum[tid][0] + smsum[tid][1] + smsum[tid][2] + smsum[tid][3];
        g_ps[((size_t)(b * S_ + mt * TM + tid)) * 16 + nt] = s;
    }
}

// ------------- GEMM2: out = (P~ @ V) * (1/rowsum)  (1-pass fp16) -------------
__global__ void __launch_bounds__(256, 2)
gemm2_kernel(const __half* __restrict__ A, const __half* __restrict__ Bt,
             float* __restrict__ Cp) {
    extern __shared__ __align__(1024) char smg[];
    const uint32_t smb = smem_u32(smg);
    float* sminv = (float*)(smg + PIPE_B);  // [128]

    const int tid = threadIdx.x;
    const int mt = blockIdx.x, nt = blockIdx.y, b = blockIdx.z;
    const int warp = tid >> 5, lane = tid & 31;
    const int wm = warp & 1, wn = warp >> 1;
    const int lrow = lane & 15;
    const int lh16 = (lane >> 4) << 4;
    const int r7 = (lane & 7) << 4;
    constexpr int NC = S_ / TK;  // 32

    const int drow = tid >> 3, cc = tid & 7;
    const uint32_t dstoff0 = (uint32_t)(drow * 128 + ((cc ^ (drow & 7)) << 4));
    const __half* gA = A  + ((size_t)b * S_ + mt * TM + drow) * S_ + cc * 8;
    const __half* gB = Bt + ((size_t)b * D_ + nt * TN + drow) * S_ + cc * 8;

    if (tid < 128) {
        const float* ps = g_ps + ((size_t)(b * S_ + mt * TM + tid)) * 16;
        float s = 0.f;
#pragma unroll
        for (int j = 0; j < 16; ++j) s += ps[j];
        sminv[tid] = 1.0f / s;
    }

    uint32_t sload = 0;
    auto issue = [&]() {
        uint32_t da = smb + sload + dstoff0;
#pragma unroll
        for (int i = 0; i < 4; ++i) {
            CP_ASYNC16(da + i * 4096,         gA + i * 32 * S_);
            CP_ASYNC16(da + BUF_B + i * 4096, gB + i * 32 * S_);
        }
        CP_COMMIT();
        gA += TK; gB += TK;
        sload += STAGE_B; if (sload == PIPE_B) sload = 0;
    };

    float acc[4][4][4];
#pragma unroll
    for (int i = 0; i < 4; ++i)
#pragma unroll
        for (int n = 0; n < 4; ++n)
#pragma unroll
            for (int r = 0; r < 4; ++r) acc[i][n][r] = 0.f;

    issue();
    issue();

    const uint32_t cA = (uint32_t)((wm * 64 + lrow) * 128);
    const uint32_t cB = (uint32_t)(BUF_B + (wn * 32 + lrow) * 128);

    uint32_t scomp = 0;
#pragma unroll 1
    for (int c = 0; c < NC; ++c) {
        if (c + 1 < NC) CP_WAIT(1);
        else            CP_WAIT(0);
        __syncthreads();
        if (c + 2 < NC) issue();

        const uint32_t uA0 = smb + scomp + cA;
        const uint32_t uB0 = smb + scomp + cB;
        scomp += STAGE_B; if (scomp == PIPE_B) scomp = 0;

#pragma unroll
        for (int ks = 0; ks < 4; ++ks) {
            const uint32_t kxr = (uint32_t)((ks * 32 + lh16) ^ r7);
            uint32_t ah[4][4], bh[2][4];
#pragma unroll
            for (int i = 0; i < 4; ++i) LDSM4(ah[i], uA0 + i * 2048 + kxr);
#pragma unroll
            for (int j = 0; j < 2; ++j) LDSM4(bh[j], uB0 + j * 2048 + kxr);
#pragma unroll
            for (int i = 0; i < 4; ++i)
#pragma unroll
                for (int n = 0; n < 4; ++n) {
                    int j = n >> 1, s = n & 1;
                    MMA_F16(acc[i][n], ah[i], bh[j][s], bh[j][s + 2]);
                }
        }
    }

    const int rloc = wm * 64 + (lane >> 2);
    const int r0 = mt * TM + rloc;
    const int cl0 = wn * 32 + (lane & 3) * 2;
#pragma unroll
    for (int i = 0; i < 4; ++i) {
        float inv_lo = sminv[rloc + i * 16];
        float inv_hi = sminv[rloc + i * 16 + 8];
#pragma unroll
        for (int n = 0; n < 4; ++n) {
            int col = nt * TN + cl0 + n * 8;
            size_t rowa = (size_t)(b * S_ + r0 + i * 16) * D_ + col;
            size_t rowb = rowa + (size_t)8 * D_;
            *reinterpret_cast<float2*>(Cp + rowa) =
                make_float2(acc[i][n][0] * inv_lo, acc[i][n][1] * inv_lo);
            *reinterpret_cast<float2*>(Cp + rowb) =
                make_float2(acc[i][n][2] * inv_hi, acc[i][n][3] * inv_hi);
        }
    }
}

// --------------------------------- launch -----------------------------------
extern "C" void kernel_launch(void* const* d_in, const int* in_sizes, int n_in,
                              void* d_out, int out_size) {
    const float* q    = (const float*)d_in[0];
    const float* k    = (const float*)d_in[1];
    const float* v    = (const float*)d_in[2];
    const float* mask = (const float*)d_in[3];
    float* out = (float*)d_out;

    cudaFuncSetAttribute(gemm1_kernel,
                         cudaFuncAttributeMaxDynamicSharedMemorySize, SMEM_G1);
    cudaFuncSetAttribute(gemm2_kernel,
                         cudaFuncAttributeMaxDynamicSharedMemorySize, SMEM_G2);

    __half *qh, *kh, *vt, *p;
    cudaGetSymbolAddress((void**)&qh, g_qh);
    cudaGetSymbolAddress((void**)&kh, g_kh);
    cudaGetSymbolAddress((void**)&vt, g_vt);
    cudaGetSymbolAddress((void**)&p,  g_p);

    conv_h_kernel<<<16384, 256>>>(q, qh);
    conv_h_kernel<<<16384, 256>>>(k, kh);
    conv_v_kernel<<<dim3(512, 8), 256>>>(v);

    gemm1_kernel<<<dim3(16, 16, 8), 256, SMEM_G1>>>(qh, kh, mask);
    gemm2_kernel<<<dim3(16, 8, 8), 256, SMEM_G2>>>(p, vt, out);
}

// round 9
// speedup vs baseline: 14.1028x; 1.0107x over previous
#include <cuda_runtime.h>
#include <cuda_fp16.h>
#include <cstdint>

// ScaledDotProductAttention B=8, S=2048, D=1024 fp32.
// HMMA fp16 1-pass both GEMMs; fused exp epilogue + fused 1/rowsum normalization.
// R9: 4-warp CTAs (2x2 of 64x64 warp tiles) -> MMA:LDSM ratio 4.0, 2 CTAs/SM.

namespace {
constexpr int BN = 8, S_ = 2048, D_ = 1024;
constexpr float SCALE = 0.03125f;          // D^-0.5
constexpr float NEGV  = -1000000000.0f;

constexpr int TM = 128, TN = 128, TK = 64;
constexpr int NT = 128;                                  // threads per CTA
constexpr uint32_t BUF_B   = 16384;                      // one 128x64 fp16 tile
constexpr uint32_t STAGE_B = 2 * BUF_B;                  // A,B
constexpr uint32_t PIPE_B  = 3 * STAGE_B;                // 98304
constexpr uint32_t SMEM_G1 = PIPE_B + 512 + 1024;        // + mask row + rowsum buf
constexpr uint32_t SMEM_G2 = PIPE_B + 512;               // + inv row buf
}  // namespace

// ------------------------- scratch (device globals) -------------------------
__device__ __align__(128) __half g_qh[(size_t)BN * S_ * D_];
__device__ __align__(128) __half g_kh[(size_t)BN * S_ * D_];
__device__ __align__(128) __half g_vt[(size_t)BN * D_ * S_];   // V^T [b][d][s]
__device__ __align__(128) __half g_p [(size_t)BN * S_ * S_];   // unnormalized exp P~
__device__ __align__(128) float  g_ps[(size_t)BN * S_ * 16];   // row partial sums

// ------------------------------- helpers ------------------------------------
__device__ __forceinline__ uint32_t smem_u32(const void* p) {
    uint32_t a;
    asm("{ .reg .u64 t; cvta.to.shared.u64 t, %1; cvt.u32.u64 %0, t; }"
        : "=r"(a) : "l"(p));
    return a;
}

#define LDSM4(r, addr) \
    asm volatile("ldmatrix.sync.aligned.m8n8.x4.shared.b16 {%0,%1,%2,%3}, [%4];" \
        : "=r"((r)[0]), "=r"((r)[1]), "=r"((r)[2]), "=r"((r)[3]) : "r"(addr))

#define MMA_F16(d, a, b0, b1) \
    asm volatile("mma.sync.aligned.m16n8k16.row.col.f32.f16.f16.f32 " \
        "{%0,%1,%2,%3}, {%4,%5,%6,%7}, {%8,%9}, {%0,%1,%2,%3};" \
        : "+f"((d)[0]), "+f"((d)[1]), "+f"((d)[2]), "+f"((d)[3]) \
        : "r"((a)[0]), "r"((a)[1]), "r"((a)[2]), "r"((a)[3]), "r"(b0), "r"(b1))

#define CP_ASYNC16(dst, src) \
    asm volatile("cp.async.cg.shared.global [%0], [%1], 16;" :: "r"(dst), "l"(src))
#define CP_COMMIT()  asm volatile("cp.async.commit_group;" ::: "memory")
#define CP_WAIT(n)   asm volatile("cp.async.wait_group %0;" :: "n"(n) : "memory")

__device__ __forceinline__ uint2 pack4(const uint16_t* h) {
    return make_uint2((uint32_t)h[0] | ((uint32_t)h[1] << 16),
                      (uint32_t)h[2] | ((uint32_t)h[3] << 16));
}

// --------------------------- convert kernels --------------------------------
__global__ void __launch_bounds__(256) conv_h_kernel(
    const float* __restrict__ src, __half* __restrict__ dst) {
    size_t e0 = ((size_t)blockIdx.x * 256 + threadIdx.x) * 4;
    float4 val = *reinterpret_cast<const float4*>(src + e0);
    uint16_t h[4];
    h[0] = __half_as_ushort(__float2half_rn(val.x));
    h[1] = __half_as_ushort(__float2half_rn(val.y));
    h[2] = __half_as_ushort(__float2half_rn(val.z));
    h[3] = __half_as_ushort(__float2half_rn(val.w));
    *reinterpret_cast<uint2*>(dst + e0) = pack4(h);
}

__global__ void __launch_bounds__(256) conv_v_kernel(const float* __restrict__ v) {
    __shared__ float tile[64][68];
    int b  = blockIdx.y;
    int st = blockIdx.x >> 4;
    int dt = blockIdx.x & 15;
    int tid = threadIdx.x;
    int i0 = tid >> 4, j4 = (tid & 15) * 4;
#pragma unroll
    for (int r = 0; r < 4; ++r) {
        int i = i0 + r * 16;
        float4 val = *reinterpret_cast<const float4*>(
            v + ((size_t)b * S_ + st * 64 + i) * D_ + dt * 64 + j4);
        tile[i][j4 + 0] = val.x; tile[i][j4 + 1] = val.y;
        tile[i][j4 + 2] = val.z; tile[i][j4 + 3] = val.w;
    }
    __syncthreads();
#pragma unroll
    for (int r = 0; r < 4; ++r) {
        int dl_ = i0 + r * 16;
        uint16_t h[4];
#pragma unroll
        for (int c = 0; c < 4; ++c)
            h[c] = __half_as_ushort(__float2half_rn(tile[j4 + c][dl_]));
        size_t off = ((size_t)b * D_ + dt * 64 + dl_) * S_ + st * 64 + j4;
        *reinterpret_cast<uint2*>(g_vt + off) = pack4(h);
    }
}

// ------------------ GEMM1: P~ = exp(QK^T*SCALE + mask) ----------------------
__global__ void __launch_bounds__(NT, 2)
gemm1_kernel(const __half* __restrict__ Ah, const __half* __restrict__ Bh,
             const float* __restrict__ mask) {
    extern __shared__ __align__(1024) char smg[];
    const uint32_t smb = smem_u32(smg);
    float* smmask = (float*)(smg + PIPE_B);
    float (*smsum)[2] = (float(*)[2])(smg + PIPE_B + 512);  // [128][2]

    const int tid = threadIdx.x;
    const int mt = blockIdx.x, nt = blockIdx.y, b = blockIdx.z;
    const int warp = tid >> 5, lane = tid & 31;
    const int wm = warp & 1, wn = warp >> 1;   // 2x2 warp grid, 64x64 tiles
    const int lrow = lane & 15;
    const int lh16 = (lane >> 4) << 4;
    const int r7 = (lane & 7) << 4;
    constexpr int NC = D_ / TK;  // 16

    // cp.async: 128 threads, 8 x 16B per tile per thread
    const int drow = tid >> 3, cc = tid & 7;
    const uint32_t dstoff0 = (uint32_t)(drow * 128 + ((cc ^ (drow & 7)) << 4));
    const __half* gA = Ah + ((size_t)b * S_ + mt * TM + drow) * D_ + cc * 8;
    const __half* gB = Bh + ((size_t)b * S_ + nt * TN + drow) * D_ + cc * 8;

    smmask[tid] = mask[(size_t)b * S_ + nt * TN + tid] * NEGV;

    uint32_t sload = 0;
    auto issue = [&]() {
        uint32_t da = smb + sload + dstoff0;
#pragma unroll
        for (int i = 0; i < 8; ++i) {
            CP_ASYNC16(da + i * 2048,         gA + i * 16 * D_);
            CP_ASYNC16(da + BUF_B + i * 2048, gB + i * 16 * D_);
        }
        CP_COMMIT();
        gA += TK; gB += TK;
        sload += STAGE_B; if (sload == PIPE_B) sload = 0;
    };

    float acc[4][8][4];
#pragma unroll
    for (int i = 0; i < 4; ++i)
#pragma unroll
        for (int n = 0; n < 8; ++n)
#pragma unroll
            for (int r = 0; r < 4; ++r) acc[i][n][r] = 0.f;

    issue();
    issue();

    const uint32_t cA = (uint32_t)((wm * 64 + lrow) * 128);
    const uint32_t cB = (uint32_t)(BUF_B + (wn * 64 + lrow) * 128);

    uint32_t scomp = 0;
#pragma unroll 1
    for (int c = 0; c < NC; ++c) {
        if (c + 1 < NC) CP_WAIT(1);
        else            CP_WAIT(0);
        __syncthreads();
        if (c + 2 < NC) issue();

        const uint32_t uA0 = smb + scomp + cA;
        const uint32_t uB0 = smb + scomp + cB;
        scomp += STAGE_B; if (scomp == PIPE_B) scomp = 0;

#pragma unroll
        for (int ks = 0; ks < 4; ++ks) {
            const uint32_t kxr = (uint32_t)((ks * 32 + lh16) ^ r7);
            uint32_t ah[4][4], bh[4][4];
#pragma unroll
            for (int i = 0; i < 4; ++i) LDSM4(ah[i], uA0 + i * 2048 + kxr);
#pragma unroll
            for (int j = 0; j < 4; ++j) LDSM4(bh[j], uB0 + j * 2048 + kxr);
#pragma unroll
            for (int i = 0; i < 4; ++i)
#pragma unroll
                for (int n = 0; n < 8; ++n) {
                    int j = n >> 1, s = n & 1;
                    MMA_F16(acc[i][n], ah[i], bh[j][s], bh[j][s + 2]);
                }
        }
    }

    // ---- epilogue: e = exp(acc*SCALE + mask), write fp16, reduce row sums ----
    const int rloc = wm * 64 + (lane >> 2);
    const int r0 = mt * TM + rloc;
    const int cl0 = wn * 64 + (lane & 3) * 2;
#pragma unroll
    for (int i = 0; i < 4; ++i) {
        float sum_lo = 0.f, sum_hi = 0.f;
#pragma unroll
        for (int n = 0; n < 8; ++n) {
            int cl = cl0 + n * 8;
            float mk0 = smmask[cl], mk1 = smmask[cl + 1];
            float e0 = __expf(acc[i][n][0] * SCALE + mk0);
            float e1 = __expf(acc[i][n][1] * SCALE + mk1);
            float e2 = __expf(acc[i][n][2] * SCALE + mk0);
            float e3 = __expf(acc[i][n][3] * SCALE + mk1);
            sum_lo += e0 + e1;
            sum_hi += e2 + e3;
            size_t rowa = (size_t)(b * S_ + r0 + i * 16) * S_ + nt * TN + cl;
            size_t rowb = rowa + (size_t)8 * S_;
            *reinterpret_cast<__half2*>(g_p + rowa) = __floats2half2_rn(e0, e1);
            *reinterpret_cast<__half2*>(g_p + rowb) = __floats2half2_rn(e2, e3);
        }
#pragma unroll
        for (int o = 1; o < 4; o <<= 1) {
            sum_lo += __shfl_xor_sync(~0u, sum_lo, o);
            sum_hi += __shfl_xor_sync(~0u, sum_hi, o);
        }
        if ((lane & 3) == 0) {
            smsum[rloc + i * 16][wn]     = sum_lo;
            smsum[rloc + i * 16 + 8][wn] = sum_hi;
        }
    }
    __syncthreads();
    {
        float s = smsum[tid][0] + smsum[tid][1];
        g_ps[((size_t)(b * S_ + mt * TM + tid)) * 16 + nt] = s;
    }
}

// ------------- GEMM2: out = (P~ @ V) * (1/rowsum)  (1-pass fp16) -------------
__global__ void __launch_bounds__(NT, 2)
gemm2_kernel(const __half* __restrict__ A, const __half* __restrict__ Bt,
             float* __restrict__ Cp) {
    extern __shared__ __align__(1024) char smg[];
    const uint32_t smb = smem_u32(smg);
    float* sminv = (float*)(smg + PIPE_B);  // [128]

    const int tid = threadIdx.x;
    const int mt = blockIdx.x, nt = blockIdx.y, b = blockIdx.z;
    const int warp = tid >> 5, lane = tid & 31;
    const int wm = warp & 1, wn = warp >> 1;
    const int lrow = lane & 15;
    const int lh16 = (lane >> 4) << 4;
    const int r7 = (lane & 7) << 4;
    constexpr int NC = S_ / TK;  // 32

    const int drow = tid >> 3, cc = tid & 7;
    const uint32_t dstoff0 = (uint32_t)(drow * 128 + ((cc ^ (drow & 7)) << 4));
    const __half* gA = A  + ((size_t)b * S_ + mt * TM + drow) * S_ + cc * 8;
    const __half* gB = Bt + ((size_t)b * D_ + nt * TN + drow) * S_ + cc * 8;

    {
        const float* ps = g_ps + ((size_t)(b * S_ + mt * TM + tid)) * 16;
        float s = 0.f;
#pragma unroll
        for (int j = 0; j < 16; ++j) s += ps[j];
        sminv[tid] = 1.0f / s;
    }

    uint32_t sload = 0;
    auto issue = [&]() {
        uint32_t da = smb + sload + dstoff0;
#pragma unroll
        for (int i = 0; i < 8; ++i) {
            CP_ASYNC16(da + i * 2048,         gA + i * 16 * S_);
            CP_ASYNC16(da + BUF_B + i * 2048, gB + i * 16 * S_);
        }
        CP_COMMIT();
        gA += TK; gB += TK;
        sload += STAGE_B; if (sload == PIPE_B) sload = 0;
    };

    float acc[4][8][4];
#pragma unroll
    for (int i = 0; i < 4; ++i)
#pragma unroll
        for (int n = 0; n < 8; ++n)
#pragma unroll
            for (int r = 0; r < 4; ++r) acc[i][n][r] = 0.f;

    issue();
    issue();

    const uint32_t cA = (uint32_t)((wm * 64 + lrow) * 128);
    const uint32_t cB = (uint32_t)(BUF_B + (wn * 64 + lrow) * 128);

    uint32_t scomp = 0;
#pragma unroll 1
    for (int c = 0; c < NC; ++c) {
        if (c + 1 < NC) CP_WAIT(1);
        else            CP_WAIT(0);
        __syncthreads();
        if (c + 2 < NC) issue();

        const uint32_t uA0 = smb + scomp + cA;
        const uint32_t uB0 = smb + scomp + cB;
        scomp += STAGE_B; if (scomp == PIPE_B) scomp = 0;

#pragma unroll
        for (int ks = 0; ks < 4; ++ks) {
            const uint32_t kxr = (uint32_t)((ks * 32 + lh16) ^ r7);
            uint32_t ah[4][4], bh[4][4];
#pragma unroll
            for (int i = 0; i < 4; ++i) LDSM4(ah[i], uA0 + i * 2048 + kxr);
#pragma unroll
            for (int j = 0; j < 4; ++j) LDSM4(bh[j], uB0 + j * 2048 + kxr);
#pragma unroll
            for (int i = 0; i < 4; ++i)
#pragma unroll
                for (int n = 0; n < 8; ++n) {
                    int j = n >> 1, s = n & 1;
                    MMA_F16(acc[i][n], ah[i], bh[j][s], bh[j][s + 2]);
                }
        }
    }

    const int rloc = wm * 64 + (lane >> 2);
    const int r0 = mt * TM + rloc;
    const int cl0 = wn * 64 + (lane & 3) * 2;
#pragma unroll
    for (int i = 0; i < 4; ++i) {
        float inv_lo = sminv[rloc + i * 16];
        float inv_hi = sminv[rloc + i * 16 + 8];
#pragma unroll
        for (int n = 0; n < 8; ++n) {
            int col = nt * TN + cl0 + n * 8;
            size_t rowa = (size_t)(b * S_ + r0 + i * 16) * D_ + col;
            size_t rowb = rowa + (size_t)8 * D_;
            *reinterpret_cast<float2*>(Cp + rowa) =
                make_float2(acc[i][n][0] * inv_lo, acc[i][n][1] * inv_lo);
            *reinterpret_cast<float2*>(Cp + rowb) =
                make_float2(acc[i][n][2] * inv_hi, acc[i][n][3] * inv_hi);
        }
    }
}

// --------------------------------- launch -----------------------------------
extern "C" void kernel_launch(void* const* d_in, const int* in_sizes, int n_in,
                              void* d_out, int out_size) {
    const float* q    = (const float*)d_in[0];
    const float* k    = (const float*)d_in[1];
    const float* v    = (const float*)d_in[2];
    const float* mask = (const float*)d_in[3];
    float* out = (float*)d_out;

    cudaFuncSetAttribute(gemm1_kernel,
                         cudaFuncAttributeMaxDynamicSharedMemorySize, SMEM_G1);
    cudaFuncSetAttribute(gemm2_kernel,
                         cudaFuncAttributeMaxDynamicSharedMemorySize, SMEM_G2);

    __half *qh, *kh, *vt, *p;
    cudaGetSymbolAddress((void**)&qh, g_qh);
    cudaGetSymbolAddress((void**)&kh, g_kh);
    cudaGetSymbolAddress((void**)&vt, g_vt);
    cudaGetSymbolAddress((void**)&p,  g_p);

    conv_h_kernel<<<16384, 256>>>(q, qh);
    conv_h_kernel<<<16384, 256>>>(k, kh);
    conv_v_kernel<<<dim3(512, 8), 256>>>(v);

    gemm1_kernel<<<dim3(16, 16, 8), NT, SMEM_G1>>>(qh, kh, mask);
    gemm2_kernel<<<dim3(16, 8, 8), NT, SMEM_G2>>>(p, vt, out);
}